// round 10
// baseline (speedup 1.0000x reference)
#include <cuda_runtime.h>
#include <math.h>
#include <stdint.h>

#define B_    2
#define NQ    1024
#define NK    2048
#define DIM_  512
#define HID_  512
#define H_    8
#define HD_   64
#define RBH   64
#define LUT_N 1024
#define LOG2E 1.4426950408889634f

// Static device scratch
__device__ float g_Q[(size_t)B_ * NQ * HID_];      // tf32-pattern, pre-scaled by 0.125*log2e
__device__ float g_K[(size_t)B_ * NK * HID_];      // tf32-pattern
__device__ float g_V[(size_t)B_ * H_ * HD_ * NK];  // tf32-pattern, TRANSPOSED [b][h][d][key]
__device__ float g_attn[(size_t)B_ * NQ * HID_];   // split-0 partial -> merged (tf32-pattern)
__device__ float g_O2[(size_t)B_ * NQ * HID_];     // split-1 partial
__device__ float g_l[2 * B_ * H_ * NQ];            // softmax denoms
__device__ float g_lut[H_ * LUT_N];                // bias(d^2) * log2e
__device__ unsigned int g_maxbits[2] = {0u, 0u};
__device__ float g_inv_step2;

// tf32-pattern copies of harness inputs
__device__ float g_QinT[(size_t)B_ * NQ * DIM_];
__device__ float g_KvT[(size_t)B_ * NK * DIM_];
__device__ float g_WqT[DIM_ * HID_];
__device__ float g_WkT[DIM_ * HID_];
__device__ float g_WvT[DIM_ * HID_];
__device__ float g_WoT[HID_ * DIM_];

// ---------------------------------------------------------------------------
__device__ __forceinline__ uint32_t f2tf(float x) {
    uint32_t r; asm("cvt.rna.tf32.f32 %0, %1;" : "=r"(r) : "f"(x)); return r;
}
__device__ __forceinline__ float ex2(float x) {
    float y; asm("ex2.approx.f32 %0, %1;" : "=f"(y) : "f"(x)); return y;
}
// pure register op: non-volatile so ptxas can interleave freely
__device__ __forceinline__ void mma8(float* d, const uint32_t* a, uint32_t b0, uint32_t b1) {
    asm("mma.sync.aligned.m16n8k8.row.col.f32.tf32.tf32.f32 "
        "{%0,%1,%2,%3}, {%4,%5,%6,%7}, {%8,%9}, {%0,%1,%2,%3};"
        : "+f"(d[0]), "+f"(d[1]), "+f"(d[2]), "+f"(d[3])
        : "r"(a[0]), "r"(a[1]), "r"(a[2]), "r"(a[3]), "r"(b0), "r"(b1));
}
__device__ __forceinline__ void ldsm4(uint32_t* r, uint32_t saddr) {
    asm volatile("ldmatrix.sync.aligned.m8n8.x4.shared.b16 {%0,%1,%2,%3}, [%4];"
        : "=r"(r[0]), "=r"(r[1]), "=r"(r[2]), "=r"(r[3]) : "r"(saddr));
}
__device__ __forceinline__ void cpa16(uint32_t s, const float* g) {
    asm volatile("cp.async.cg.shared.global [%0], [%1], 16;" :: "r"(s), "l"(g));
}
__device__ __forceinline__ uint32_t s2u(const void* p) {
    return (uint32_t)__cvta_generic_to_shared(p);
}
__device__ __forceinline__ uint32_t ldr(const float* p) {
    return __float_as_uint(*p);
}

// ---------------------------------------------------------------------------
// conv + norm fused
// ---------------------------------------------------------------------------
__global__ __launch_bounds__(256) void conv_kernel(
    const float4* __restrict__ qin, const float4* __restrict__ kvin,
    const float4* __restrict__ wq, const float4* __restrict__ wk,
    const float4* __restrict__ wv, const float4* __restrict__ wo,
    const float* __restrict__ qc, const float* __restrict__ kc)
{
    int i = blockIdx.x * 256 + threadIdx.x;
    float4 v; float4* dst;
    if      (i < 262144) { v = qin[i];            dst = (float4*)g_QinT + i; }
    else if (i < 786432) { v = kvin[i - 262144];  dst = (float4*)g_KvT + (i - 262144); }
    else if (i < 851968) { v = wq[i - 786432];    dst = (float4*)g_WqT + (i - 786432); }
    else if (i < 917504) { v = wk[i - 851968];    dst = (float4*)g_WkT + (i - 851968); }
    else if (i < 983040) { v = wv[i - 917504];    dst = (float4*)g_WvT + (i - 917504); }
    else                 { v = wo[i - 983040];    dst = (float4*)g_WoT + (i - 983040); }
    v.x = __uint_as_float(f2tf(v.x));
    v.y = __uint_as_float(f2tf(v.y));
    v.z = __uint_as_float(f2tf(v.z));
    v.w = __uint_as_float(f2tf(v.w));
    *dst = v;

    const int NQT = B_ * NQ, NKT = B_ * NK;
    if (i < NQT + NKT) {
        float n; int which;
        if (i < NQT) {
            float x = qc[i*3], y = qc[i*3+1], z = qc[i*3+2];
            n = sqrtf(fmaf(x,x,fmaf(y,y,z*z))); which = 0;
        } else {
            int j = i - NQT;
            float x = kc[j*3], y = kc[j*3+1], z = kc[j*3+2];
            n = sqrtf(fmaf(x,x,fmaf(y,y,z*z))); which = 1;
        }
        atomicMax(&g_maxbits[which], __float_as_uint(n));
    }
}

__global__ __launch_bounds__(256) void lut_kernel(
    const float* __restrict__ W1, const float* __restrict__ b1,
    const float* __restrict__ W2, const float* __restrict__ b2)
{
    __shared__ float sW1[RBH], sb1[RBH], sW2[RBH * H_];
    int t = threadIdx.x;
    if (t < RBH) { sW1[t] = W1[t]; sb1[t] = b1[t]; }
    for (int i = t; i < RBH * H_; i += 256) sW2[i] = W2[i];
    __syncthreads();

    float dmax = __uint_as_float(g_maxbits[0]) + __uint_as_float(g_maxbits[1]) + 1e-3f;
    float step2 = dmax * dmax / (float)(LUT_N - 1);
    if (blockIdx.x == 0 && t == 0) g_inv_step2 = 1.0f / step2;

    int i = blockIdx.x * 256 + t;
    if (i >= LUT_N) return;
    float d = sqrtf(step2 * (float)i);

    float o[H_];
    #pragma unroll
    for (int hh = 0; hh < H_; hh++) o[hh] = b2[hh];
    #pragma unroll 8
    for (int j = 0; j < RBH; j++) {
        float x = fmaf(d, sW1[j], sb1[j]);
        float s = __fdividef(x, 1.0f + __expf(-x));
        #pragma unroll
        for (int hh = 0; hh < H_; hh++)
            o[hh] = fmaf(s, sW2[j * H_ + hh], o[hh]);
    }
    #pragma unroll
    for (int hh = 0; hh < H_; hh++)
        g_lut[hh * LUT_N + i] = o[hh] * LOG2E;
}

// ---------------------------------------------------------------------------
// Raw-tf32 GEMM body, BMxBN, BK=16, 3-stage cp.async, 256 thr, LDSM A-frags.
// mode: 0 plain store, 1 f2tf, 2 f2tf(x*QSC), 3 f2tf + transposed V store
// ---------------------------------------------------------------------------
#define QSC (0.125f * LOG2E)

template<int BM, int BN>
__device__ __forceinline__ void gemm_raw_body(
    const float* __restrict__ A, const float* __restrict__ Bm,
    float* __restrict__ C, int N, int K, int row0, int mode, float* sm)
{
    constexpr int BSr = BN + 8;
    constexpr int ASZ = BM * 20, BSZ = 16 * BSr;
    constexpr int MF  = BM / 64;
    constexpr int NF  = BN / 16;
    float* As = sm;
    float* Bs = sm + 3 * ASZ;

    const int tid = threadIdx.x;
    const int lane = tid & 31, wid = tid >> 5;
    const int wm = (wid >> 1) * (BM / 4), wn = (wid & 1) * (BN / 2);
    const int col0 = blockIdx.x * BN;
    const int lq = lane >> 2, lr = lane & 3;

    const int a_lrow = ((lane >> 3) & 1) * 8 + (lane & 7);
    const int a_lcol = (lane >> 4) * 4;

    const int ar = (BM == 128) ? (tid >> 1) : (tid >> 2);
    const int ac = (BM == 128) ? ((tid & 1) * 8) : ((tid & 3) * 4);
    const int bk = tid >> 4, bn = (tid & 15) * (BN / 16);

    float acc[MF][NF][4] = {};

    auto issue = [&](int k0) {
        const int st = (k0 >> 4) % 3;
        uint32_t a_s = s2u(&As[st * ASZ + ar * 20 + ac]);
        const float* ag = A + (size_t)(row0 + ar) * K + k0 + ac;
        cpa16(a_s, ag);
        if (BM == 128) cpa16(a_s + 16, ag + 4);
        uint32_t b_s = s2u(&Bs[st * BSZ + bk * BSr + bn]);
        const float* bg = Bm + (size_t)(k0 + bk) * N + col0 + bn;
        cpa16(b_s, bg);
        if (BN == 128) cpa16(b_s + 16, bg + 4);
        asm volatile("cp.async.commit_group;" ::: "memory");
    };

    issue(0); issue(16);

    for (int k0 = 0; k0 < K; k0 += 16) {
        if (k0 + 32 < K) {
            asm volatile("cp.async.wait_group 1;" ::: "memory");
            __syncthreads();
            issue(k0 + 32);
        } else if (k0 + 16 < K) {
            asm volatile("cp.async.wait_group 1;" ::: "memory");
            __syncthreads();
        } else {
            asm volatile("cp.async.wait_group 0;" ::: "memory");
            __syncthreads();
        }
        const int st = (k0 >> 4) % 3;
        const float* Ab = As + st * ASZ;
        const float* Bb = Bs + st * BSZ;

        #pragma unroll
        for (int s = 0; s < 2; s++) {
            const int kc_ = s * 8 + lr;
            uint32_t af[MF][4], bfr[NF][2];
            #pragma unroll
            for (int mf = 0; mf < MF; mf++)
                ldsm4(af[mf], s2u(Ab) +
                      ((wm + mf * 16 + a_lrow) * 20 + s * 8 + a_lcol) * 4);
            #pragma unroll
            for (int nf = 0; nf < NF; nf++) {
                const int cc = wn + nf * 8 + lq;
                bfr[nf][0] = ldr(&Bb[kc_ * BSr + cc]);
                bfr[nf][1] = ldr(&Bb[(kc_ + 4) * BSr + cc]);
            }
            #pragma unroll
            for (int mf = 0; mf < MF; mf++)
                #pragma unroll
                for (int nf = 0; nf < NF; nf++)
                    mma8(acc[mf][nf], af[mf], bfr[nf][0], bfr[nf][1]);
        }
    }

    #pragma unroll
    for (int mf = 0; mf < MF; mf++)
        #pragma unroll
        for (int nf = 0; nf < NF; nf++) {
            const int r = row0 + wm + mf * 16 + lq;
            const int c = col0 + wn + nf * 8 + 2 * lr;
            float v[4] = {acc[mf][nf][0], acc[mf][nf][1], acc[mf][nf][2], acc[mf][nf][3]};
            if (mode == 1 || mode == 3) {
                #pragma unroll
                for (int u = 0; u < 4; u++) v[u] = __uint_as_float(f2tf(v[u]));
            } else if (mode == 2) {
                #pragma unroll
                for (int u = 0; u < 4; u++) v[u] = __uint_as_float(f2tf(v[u] * QSC));
            }
            if (mode == 3) {
                // transposed V store: r = b*2048 + key, c/c+1 = h*64 + d
                #pragma unroll
                for (int rw = 0; rw < 2; rw++) {
                    const int rr = r + rw * 8;
                    const int bb = rr >> 11, key = rr & 2047;
                    #pragma unroll
                    for (int cc = 0; cc < 2; cc++) {
                        const int col = c + cc;
                        C[(((size_t)bb * H_ + (col >> 6)) * HD_ + (col & 63)) * NK + key]
                            = v[rw * 2 + cc];
                    }
                }
            } else {
                *(float2*)&C[(size_t)r * N + c]       = make_float2(v[0], v[1]);
                *(float2*)&C[(size_t)(r + 8) * N + c] = make_float2(v[2], v[3]);
            }
        }
}

#define QKV_SMEM (3 * (128 * 20 + 16 * 136) * 4)
#define OUT_SMEM (3 * (64 * 20 + 16 * 72) * 4)

__global__ __launch_bounds__(256, 2) void gemm_qkv_kernel()
{
    extern __shared__ float gsm[];
    int by = blockIdx.y;
    const float *A, *Bw; float* C; int mode;
    if (by < 16)      { A = g_QinT; Bw = g_WqT; C = g_Q; mode = 2; }
    else if (by < 48) { A = g_KvT;  Bw = g_WkT; C = g_K; mode = 1; by -= 16; }
    else              { A = g_KvT;  Bw = g_WvT; C = g_V; mode = 3; by -= 48; }
    gemm_raw_body<128, 128>(A, Bw, C, HID_, DIM_, by * 128, mode, gsm);
}

__global__ __launch_bounds__(256, 3) void gemm_out_kernel(float* __restrict__ out)
{
    extern __shared__ float gsm[];
    gemm_raw_body<64, 64>(g_attn, g_WoT, out, DIM_, HID_, blockIdx.y * 64, 0, gsm);
}

// ---------------------------------------------------------------------------
// TF32 flash attention, CTA split-K(2), no-max softmax, full-LDSM fragments.
// CTA = 64 q x 1024 keys, 128 thr / 4 warps, 32-key tiles, 4 CTAs/SM.
// V held transposed in smem ([d][key]) so PV B-frags come from ldmatrix.
// ---------------------------------------------------------------------------
#define AKT    32
#define KV_STR 76
#define VT_STR 36    // V^T tile: 64 d-rows x 32 keys, stride 36 (conflict-free)
#define P_STR  36
#define KBUF   (AKT * KV_STR)
#define VBUF   (HD_ * VT_STR)            // 2304
#define OFF_K   0                        // 2*2432 = 4864
#define OFF_V   4864                     // 2*2304 = 4608
#define OFF_P   9472                     // 64*36  = 2304
#define OFF_LUT 11776                    // 1024 float2 = 2048 words
#define ATT_SMEM_FLOATS 13824            // 55296 B

__global__ __launch_bounds__(128, 4) void attn_kernel(
    const float* __restrict__ qc, const float* __restrict__ kc)
{
    extern __shared__ float sm[];
    float2*   slut2 = (float2*)(sm + OFF_LUT);
    uint32_t* Pu    = (uint32_t*)(sm + OFF_P);

    const int b   = blockIdx.z >> 1;
    const int ks  = blockIdx.z & 1;
    const int h   = blockIdx.y;
    const int q0  = blockIdx.x * 64;
    const int tid = threadIdx.x;
    const int lane = tid & 31;
    const int w    = tid >> 5;
    const int lq   = lane >> 2;
    const int lr   = lane & 3;
    const int kstart = ks * (NK / 2);

    {
        const float* lb = g_lut + h * LUT_N;
        for (int i = tid; i < LUT_N - 1; i += 128)
            slut2[i] = make_float2(lb[i], lb[i + 1]);
    }
    const float inv_step2 = g_inv_step2;

    // LDSM lane geometry (identical pattern for K, V^T, P)
    const int k_lane_off  = (lane & 7) * KV_STR + (lane >> 3) * 4;
    const int vt_lane_off = (lane & 7) * VT_STR + (lane >> 3) * 4;
    const uint32_t ext_addr_off = (uint32_t)(lane * KV_STR + 64) * 4;
    const int p_lane_off = (w * 16 + ((lane >> 3) & 1) * 8 + (lane & 7)) * P_STR
                         + (lane >> 4) * 4;

    uint32_t qa[8][4], qa2[4];
    float qn2s0, qn2s1;
    {
        const size_t r0 = ((size_t)(b * NQ + q0 + w * 16 + lq)) * HID_ + h * HD_;
        const size_t r1 = r0 + 8 * HID_;
        #pragma unroll
        for (int kss = 0; kss < 8; kss++) {
            qa[kss][0] = ldr(&g_Q[r0 + kss * 8 + lr]);
            qa[kss][1] = ldr(&g_Q[r1 + kss * 8 + lr]);
            qa[kss][2] = ldr(&g_Q[r0 + kss * 8 + lr + 4]);
            qa[kss][3] = ldr(&g_Q[r1 + kss * 8 + lr + 4]);
        }
        const float* p0 = qc + ((size_t)b * NQ + q0 + w * 16 + lq) * 3;
        const float* p1 = p0 + 8 * 3;
        float c0[4] = {p0[0], p0[1], p0[2], 1.0f};
        float c1[4] = {p1[0], p1[1], p1[2], 1.0f};
        qa2[0] = f2tf(c0[lr]);
        qa2[1] = f2tf(c1[lr]);
        qa2[2] = 0u; qa2[3] = 0u;
        qn2s0 = fmaf(c0[0], c0[0], fmaf(c0[1], c0[1], c0[2] * c0[2])) * inv_step2;
        qn2s1 = fmaf(c1[0], c1[0], fmaf(c1[1], c1[1], c1[2] * c1[2])) * inv_step2;
    }

    float of[8][4] = {};
    float l0 = 0.f, l1 = 0.f;

    const float* Kp  = g_K + ((size_t)b * NK) * HID_ + h * HD_;
    const float* Vpt = g_V + ((size_t)(b * H_ + h) * HD_) * NK;   // [d][key]
    const float* kcb = kc + (size_t)b * NK * 3;

    const int lkey = tid >> 2;            // K loader: key row
    const int qo   = (tid & 3) * 16;
    const int vrow = tid >> 1;            // V loader: d row (0..63)
    const int vcb  = (tid & 1) * 16;      // col base within 32-key row

    auto issue = [&](int t, int bf) {
        const size_t kg = (size_t)(kstart + t * AKT + lkey) * HID_ + qo;
        uint32_t kd = s2u(sm + OFF_K + bf * KBUF + lkey * KV_STR + qo);
        #pragma unroll
        for (int u = 0; u < 4; u++) cpa16(kd + u * 16, Kp + kg + u * 4);
        const float* vg = Vpt + (size_t)vrow * NK + kstart + t * AKT + vcb;
        uint32_t vd = s2u(sm + OFF_V + bf * VBUF + vrow * VT_STR + vcb);
        #pragma unroll
        for (int u = 0; u < 4; u++) cpa16(vd + u * 16, vg + u * 4);
        asm volatile("cp.async.commit_group;" ::: "memory");
    };

    float ccx = 0.f, ccy = 0.f, ccz = 0.f;
    if (tid < AKT) {
        const float* p = kcb + (size_t)(kstart + tid) * 3;
        ccx = p[0]; ccy = p[1]; ccz = p[2];
    }

    issue(0, 0);
    int buf = 0;
    const int NT = (NK / 2) / AKT;
    const uint32_t zero = 0u;

    for (int t = 0; t < NT; t++) {
        const bool more = (t + 1) < NT;
        if (more) {
            issue(t + 1, buf ^ 1);
            asm volatile("cp.async.wait_group 1;" ::: "memory");
        } else {
            asm volatile("cp.async.wait_group 0;" ::: "memory");
        }
        if (tid < AKT) {
            float* ext = sm + OFF_K + buf * KBUF + tid * KV_STR + 64;
            ext[0] = __uint_as_float(f2tf(-2.f * ccx * inv_step2));
            ext[1] = __uint_as_float(f2tf(-2.f * ccy * inv_step2));
            ext[2] = __uint_as_float(f2tf(-2.f * ccz * inv_step2));
            ext[3] = __uint_as_float(f2tf(
                fmaf(ccx, ccx, fmaf(ccy, ccy, ccz * ccz)) * inv_step2));
        }
        __syncthreads();
        if (more && tid < AKT) {
            const float* p = kcb + (size_t)(kstart + (t + 1) * AKT + tid) * 3;
            ccx = __ldg(p); ccy = __ldg(p + 1); ccz = __ldg(p + 2);
        }

        const float* Kb = sm + OFF_K + buf * KBUF;
        const uint32_t kb_s = s2u(Kb);
        const uint32_t vb_s = s2u(sm + OFF_V + buf * VBUF);

        // ---- QK^T via LDSM ----
        float sacc[4][4] = {};
        #pragma unroll
        for (int nf = 0; nf < 4; nf++) {
            const uint32_t kbase = kb_s + (uint32_t)(nf * 8 * KV_STR + k_lane_off) * 4;
            #pragma unroll
            for (int j = 0; j < 4; j++) {
                uint32_t kb[4];
                ldsm4(kb, kbase + j * 64);
                mma8(sacc[nf], qa[2*j],     kb[0], kb[1]);
                mma8(sacc[nf], qa[2*j + 1], kb[2], kb[3]);
            }
        }

        // ---- d^2 ext fragments ----
        uint32_t eb[4];
        ldsm4(eb, kb_s + ext_addr_off);

        // ---- bias + no-max softmax ----
        float ps0 = 0.f, ps1 = 0.f;
        const int prow0 = (w * 16 + lq) * P_STR;
        const int prow1 = prow0 + 8 * P_STR;
        #pragma unroll
        for (int nf = 0; nf < 4; nf++) {
            float dd4[4] = {qn2s0, qn2s0, qn2s1, qn2s1};
            mma8(dd4, qa2, eb[nf], zero);
            float p4[4];
            #pragma unroll
            for (int j = 0; j < 4; j++) {
                float u = dd4[j];
                int ii = (int)u; ii = min(max(ii, 0), LUT_N - 2);
                float fr = u - (float)ii;
                float2 lh = slut2[ii];
                float lg = sacc[nf][j] + fmaf(fr, lh.y - lh.x, lh.x);
                p4[j] = ex2(lg);
            }
            ps0 += p4[0] + p4[1];
            ps1 += p4[2] + p4[3];
            const int c0 = nf * 8 + 2 * lr;
            *(uint2*)&Pu[prow0 + c0] = make_uint2(f2tf(p4[0]), f2tf(p4[1]));
            *(uint2*)&Pu[prow1 + c0] = make_uint2(f2tf(p4[2]), f2tf(p4[3]));
        }
        l0 += ps0;
        l1 += ps1;
        __syncwarp();

        // ---- P V (all fragments via LDSM) ----
        const uint32_t pu_s = s2u(Pu);
        uint32_t pa[4][4];
        #pragma unroll
        for (int kst = 0; kst < 4; kst++)
            ldsm4(pa[kst], pu_s + (uint32_t)(p_lane_off + kst * 8) * 4);
        #pragma unroll
        for (int nf = 0; nf < 8; nf++) {
            const uint32_t vbase = vb_s + (uint32_t)(nf * 8 * VT_STR + vt_lane_off) * 4;
            uint32_t vb0[4], vb1[4];
            ldsm4(vb0, vbase);          // keys 0-15  (kst 0,1)
            ldsm4(vb1, vbase + 64);     // keys 16-31 (kst 2,3)
            mma8(of[nf], pa[0], vb0[0], vb0[1]);
            mma8(of[nf], pa[1], vb0[2], vb0[3]);
            mma8(of[nf], pa[2], vb1[0], vb1[1]);
            mma8(of[nf], pa[3], vb1[2], vb1[3]);
        }

        __syncthreads();
        buf ^= 1;
    }

    // epilogue
    float* pO = ks ? g_O2 : g_attn;
    const size_t r0 = ((size_t)(b * NQ + q0 + w * 16 + lq)) * HID_ + h * HD_;
    const size_t r1 = r0 + 8 * HID_;
    #pragma unroll
    for (int nf = 0; nf < 8; nf++) {
        const int c = nf * 8 + 2 * lr;
        *(float2*)&pO[r0 + c] = make_float2(of[nf][0], of[nf][1]);
        *(float2*)&pO[r1 + c] = make_float2(of[nf][2], of[nf][3]);
    }
    l0 += __shfl_xor_sync(0xffffffffu, l0, 1);
    l0 += __shfl_xor_sync(0xffffffffu, l0, 2);
    l1 += __shfl_xor_sync(0xffffffffu, l1, 1);
    l1 += __shfl_xor_sync(0xffffffffu, l1, 2);
    if (lr == 0) {
        const size_t base = (((size_t)ks * B_ + b) * H_ + h) * NQ;
        const int qr = q0 + w * 16 + lq;
        g_l[base + qr]     = l0;
        g_l[base + qr + 8] = l1;
    }
}

// ---------------------------------------------------------------------------
__global__ __launch_bounds__(512) void merge_kernel()
{
    const int row = blockIdx.x;
    const int b = row >> 10;
    const int q = row & 1023;
    const int c = threadIdx.x;
    const int h = c >> 6;

    const float lA = g_l[(((size_t)0 * B_ + b) * H_ + h) * NQ + q];
    const float lB = g_l[(((size_t)1 * B_ + b) * H_ + h) * NQ + q];
    const float inv = __fdividef(1.f, lA + lB);

    const size_t o = (size_t)row * HID_ + c;
    g_attn[o] = __uint_as_float(f2tf((g_attn[o] + g_O2[o]) * inv));
}

// ---------------------------------------------------------------------------
extern "C" void kernel_launch(void* const* d_in, const int* in_sizes, int n_in,
                              void* d_out, int out_size)
{
    const float* q_in      = (const float*)d_in[0];
    const float* kv_in     = (const float*)d_in[1];
    const float* q_coords  = (const float*)d_in[2];
    const float* kv_coords = (const float*)d_in[3];
    const float* Wq        = (const float*)d_in[4];
    const float* Wk        = (const float*)d_in[5];
    const float* Wv        = (const float*)d_in[6];
    const float* Wo        = (const float*)d_in[7];
    const float* W1        = (const float*)d_in[8];
    const float* b1        = (const float*)d_in[9];
    const float* W2        = (const float*)d_in[10];
    const float* b2        = (const float*)d_in[11];
    float* out             = (float*)d_out;

    static bool attr_set = false;
    if (!attr_set) {
        cudaFuncSetAttribute(attn_kernel,
            cudaFuncAttributeMaxDynamicSharedMemorySize, ATT_SMEM_FLOATS * 4);
        cudaFuncSetAttribute(gemm_qkv_kernel,
            cudaFuncAttributeMaxDynamicSharedMemorySize, QKV_SMEM);
        cudaFuncSetAttribute(gemm_out_kernel,
            cudaFuncAttributeMaxDynamicSharedMemorySize, OUT_SMEM);
        attr_set = true;
    }

    conv_kernel<<<4096, 256>>>((const float4*)q_in, (const float4*)kv_in,
                               (const float4*)Wq, (const float4*)Wk,
                               (const float4*)Wv, (const float4*)Wo,
                               q_coords, kv_coords);
    lut_kernel<<<(LUT_N + 255) / 256, 256>>>(W1, b1, W2, b2);

    gemm_qkv_kernel<<<dim3(HID_ / 128, 80), 256, QKV_SMEM>>>();

    attn_kernel<<<dim3(NQ / 64, H_, B_ * 2), 128, ATT_SMEM_FLOATS * 4>>>(
        q_coords, kv_coords);

    merge_kernel<<<B_ * NQ, 512>>>();

    gemm_out_kernel<<<dim3(DIM_ / 64, (B_ * NQ) / 64), 256, OUT_SMEM>>>(out);
}

// round 11
// speedup vs baseline: 1.0085x; 1.0085x over previous
#include <cuda_runtime.h>
#include <math.h>
#include <stdint.h>

#define B_    2
#define NQ    1024
#define NK    2048
#define DIM_  512
#define HID_  512
#define H_    8
#define HD_   64
#define RBH   64
#define LUT_N 1024
#define LOG2E 1.4426950408889634f

// Static device scratch
__device__ float g_Q[(size_t)B_ * NQ * HID_];      // tf32-pattern, pre-scaled by 0.125*log2e
__device__ float g_K[(size_t)B_ * NK * HID_];      // tf32-pattern
__device__ float g_V[(size_t)B_ * H_ * HD_ * NK];  // tf32-pattern, TRANSPOSED [b][h][d][key]
__device__ float g_attn[(size_t)B_ * NQ * HID_];   // split-0 partial -> merged (tf32-pattern)
__device__ float g_O2[(size_t)B_ * NQ * HID_];     // split-1 partial
__device__ float g_l[2 * B_ * H_ * NQ];            // softmax denoms
__device__ float g_lut[H_ * LUT_N];                // bias(d^2) * log2e
__device__ float4 g_ext[B_ * NK];                  // per-key d^2 GEMM operand (tf32 bits)
__device__ unsigned int g_maxbits[2] = {0u, 0u};
__device__ float g_inv_step2;

// tf32-pattern copies of harness inputs
__device__ float g_QinT[(size_t)B_ * NQ * DIM_];
__device__ float g_KvT[(size_t)B_ * NK * DIM_];
__device__ float g_WqT[DIM_ * HID_];
__device__ float g_WkT[DIM_ * HID_];
__device__ float g_WvT[DIM_ * HID_];
__device__ float g_WoT[HID_ * DIM_];

// ---------------------------------------------------------------------------
__device__ __forceinline__ uint32_t f2tf(float x) {
    uint32_t r; asm("cvt.rna.tf32.f32 %0, %1;" : "=r"(r) : "f"(x)); return r;
}
__device__ __forceinline__ float ex2(float x) {
    float y; asm("ex2.approx.f32 %0, %1;" : "=f"(y) : "f"(x)); return y;
}
__device__ __forceinline__ void mma8(float* d, const uint32_t* a, uint32_t b0, uint32_t b1) {
    asm("mma.sync.aligned.m16n8k8.row.col.f32.tf32.tf32.f32 "
        "{%0,%1,%2,%3}, {%4,%5,%6,%7}, {%8,%9}, {%0,%1,%2,%3};"
        : "+f"(d[0]), "+f"(d[1]), "+f"(d[2]), "+f"(d[3])
        : "r"(a[0]), "r"(a[1]), "r"(a[2]), "r"(a[3]), "r"(b0), "r"(b1));
}
__device__ __forceinline__ void ldsm4(uint32_t* r, uint32_t saddr) {
    asm volatile("ldmatrix.sync.aligned.m8n8.x4.shared.b16 {%0,%1,%2,%3}, [%4];"
        : "=r"(r[0]), "=r"(r[1]), "=r"(r[2]), "=r"(r[3]) : "r"(saddr));
}
__device__ __forceinline__ void cpa16(uint32_t s, const float* g) {
    asm volatile("cp.async.cg.shared.global [%0], [%1], 16;" :: "r"(s), "l"(g));
}
__device__ __forceinline__ uint32_t s2u(const void* p) {
    return (uint32_t)__cvta_generic_to_shared(p);
}
__device__ __forceinline__ uint32_t ldr(const float* p) {
    return __float_as_uint(*p);
}

// ---------------------------------------------------------------------------
// conv + norm fused
// ---------------------------------------------------------------------------
__global__ __launch_bounds__(256) void conv_kernel(
    const float4* __restrict__ qin, const float4* __restrict__ kvin,
    const float4* __restrict__ wq, const float4* __restrict__ wk,
    const float4* __restrict__ wv, const float4* __restrict__ wo,
    const float* __restrict__ qc, const float* __restrict__ kc)
{
    int i = blockIdx.x * 256 + threadIdx.x;
    float4 v; float4* dst;
    if      (i < 262144) { v = qin[i];            dst = (float4*)g_QinT + i; }
    else if (i < 786432) { v = kvin[i - 262144];  dst = (float4*)g_KvT + (i - 262144); }
    else if (i < 851968) { v = wq[i - 786432];    dst = (float4*)g_WqT + (i - 786432); }
    else if (i < 917504) { v = wk[i - 851968];    dst = (float4*)g_WkT + (i - 851968); }
    else if (i < 983040) { v = wv[i - 917504];    dst = (float4*)g_WvT + (i - 917504); }
    else                 { v = wo[i - 983040];    dst = (float4*)g_WoT + (i - 983040); }
    v.x = __uint_as_float(f2tf(v.x));
    v.y = __uint_as_float(f2tf(v.y));
    v.z = __uint_as_float(f2tf(v.z));
    v.w = __uint_as_float(f2tf(v.w));
    *dst = v;

    const int NQT = B_ * NQ, NKT = B_ * NK;
    if (i < NQT + NKT) {
        float n; int which;
        if (i < NQT) {
            float x = qc[i*3], y = qc[i*3+1], z = qc[i*3+2];
            n = sqrtf(fmaf(x,x,fmaf(y,y,z*z))); which = 0;
        } else {
            int j = i - NQT;
            float x = kc[j*3], y = kc[j*3+1], z = kc[j*3+2];
            n = sqrtf(fmaf(x,x,fmaf(y,y,z*z))); which = 1;
        }
        atomicMax(&g_maxbits[which], __float_as_uint(n));
    }
}

// ---------------------------------------------------------------------------
// lut_kernel: blocks 0-3 build the per-head LUT; blocks 4-19 build g_ext
// ---------------------------------------------------------------------------
__global__ __launch_bounds__(256) void lut_kernel(
    const float* __restrict__ W1, const float* __restrict__ b1,
    const float* __restrict__ W2, const float* __restrict__ b2,
    const float* __restrict__ kc)
{
    const int blk = blockIdx.x;
    const int t = threadIdx.x;
    const float dmax = __uint_as_float(g_maxbits[0]) + __uint_as_float(g_maxbits[1]) + 1e-3f;
    const float step2 = dmax * dmax / (float)(LUT_N - 1);
    const float is2 = 1.0f / step2;

    if (blk >= 4) {
        // ext table: one key per thread
        const int j = (blk - 4) * 256 + t;      // 0..4095 = b*NK + key
        const float* p = kc + (size_t)j * 3;
        const float x = p[0], y = p[1], z = p[2];
        float4 e;
        e.x = __uint_as_float(f2tf(-2.f * x * is2));
        e.y = __uint_as_float(f2tf(-2.f * y * is2));
        e.z = __uint_as_float(f2tf(-2.f * z * is2));
        e.w = __uint_as_float(f2tf(fmaf(x, x, fmaf(y, y, z * z)) * is2));
        g_ext[j] = e;
        return;
    }

    __shared__ float sW1[RBH], sb1[RBH], sW2[RBH * H_];
    if (t < RBH) { sW1[t] = W1[t]; sb1[t] = b1[t]; }
    for (int i = t; i < RBH * H_; i += 256) sW2[i] = W2[i];
    __syncthreads();

    if (blk == 0 && t == 0) g_inv_step2 = is2;

    int i = blk * 256 + t;
    if (i >= LUT_N) return;
    float d = sqrtf(step2 * (float)i);

    float o[H_];
    #pragma unroll
    for (int hh = 0; hh < H_; hh++) o[hh] = b2[hh];
    #pragma unroll 8
    for (int j = 0; j < RBH; j++) {
        float x = fmaf(d, sW1[j], sb1[j]);
        float s = __fdividef(x, 1.0f + __expf(-x));
        #pragma unroll
        for (int hh = 0; hh < H_; hh++)
            o[hh] = fmaf(s, sW2[j * H_ + hh], o[hh]);
    }
    #pragma unroll
    for (int hh = 0; hh < H_; hh++)
        g_lut[hh * LUT_N + i] = o[hh] * LOG2E;
}

// ---------------------------------------------------------------------------
// Raw-tf32 GEMM body, BMxBN, BK=16, 3-stage cp.async, 256 thr, LDSM A-frags.
// mode: 0 plain store, 1 f2tf, 2 f2tf(x*QSC), 3 f2tf + transposed V store
// ---------------------------------------------------------------------------
#define QSC (0.125f * LOG2E)

template<int BM, int BN>
__device__ __forceinline__ void gemm_raw_body(
    const float* __restrict__ A, const float* __restrict__ Bm,
    float* __restrict__ C, int N, int K, int row0, int mode, float* sm)
{
    constexpr int BSr = BN + 8;
    constexpr int ASZ = BM * 20, BSZ = 16 * BSr;
    constexpr int MF  = BM / 64;
    constexpr int NF  = BN / 16;
    float* As = sm;
    float* Bs = sm + 3 * ASZ;

    const int tid = threadIdx.x;
    const int lane = tid & 31, wid = tid >> 5;
    const int wm = (wid >> 1) * (BM / 4), wn = (wid & 1) * (BN / 2);
    const int col0 = blockIdx.x * BN;
    const int lq = lane >> 2, lr = lane & 3;

    const int a_lrow = ((lane >> 3) & 1) * 8 + (lane & 7);
    const int a_lcol = (lane >> 4) * 4;

    const int ar = (BM == 128) ? (tid >> 1) : (tid >> 2);
    const int ac = (BM == 128) ? ((tid & 1) * 8) : ((tid & 3) * 4);
    const int bk = tid >> 4, bn = (tid & 15) * (BN / 16);

    float acc[MF][NF][4] = {};

    auto issue = [&](int k0) {
        const int st = (k0 >> 4) % 3;
        uint32_t a_s = s2u(&As[st * ASZ + ar * 20 + ac]);
        const float* ag = A + (size_t)(row0 + ar) * K + k0 + ac;
        cpa16(a_s, ag);
        if (BM == 128) cpa16(a_s + 16, ag + 4);
        uint32_t b_s = s2u(&Bs[st * BSZ + bk * BSr + bn]);
        const float* bg = Bm + (size_t)(k0 + bk) * N + col0 + bn;
        cpa16(b_s, bg);
        if (BN == 128) cpa16(b_s + 16, bg + 4);
        asm volatile("cp.async.commit_group;" ::: "memory");
    };

    issue(0); issue(16);

    for (int k0 = 0; k0 < K; k0 += 16) {
        if (k0 + 32 < K) {
            asm volatile("cp.async.wait_group 1;" ::: "memory");
            __syncthreads();
            issue(k0 + 32);
        } else if (k0 + 16 < K) {
            asm volatile("cp.async.wait_group 1;" ::: "memory");
            __syncthreads();
        } else {
            asm volatile("cp.async.wait_group 0;" ::: "memory");
            __syncthreads();
        }
        const int st = (k0 >> 4) % 3;
        const float* Ab = As + st * ASZ;
        const float* Bb = Bs + st * BSZ;

        #pragma unroll
        for (int s = 0; s < 2; s++) {
            const int kc_ = s * 8 + lr;
            uint32_t af[MF][4], bfr[NF][2];
            #pragma unroll
            for (int mf = 0; mf < MF; mf++)
                ldsm4(af[mf], s2u(Ab) +
                      ((wm + mf * 16 + a_lrow) * 20 + s * 8 + a_lcol) * 4);
            #pragma unroll
            for (int nf = 0; nf < NF; nf++) {
                const int cc = wn + nf * 8 + lq;
                bfr[nf][0] = ldr(&Bb[kc_ * BSr + cc]);
                bfr[nf][1] = ldr(&Bb[(kc_ + 4) * BSr + cc]);
            }
            #pragma unroll
            for (int mf = 0; mf < MF; mf++)
                #pragma unroll
                for (int nf = 0; nf < NF; nf++)
                    mma8(acc[mf][nf], af[mf], bfr[nf][0], bfr[nf][1]);
        }
    }

    #pragma unroll
    for (int mf = 0; mf < MF; mf++)
        #pragma unroll
        for (int nf = 0; nf < NF; nf++) {
            const int r = row0 + wm + mf * 16 + lq;
            const int c = col0 + wn + nf * 8 + 2 * lr;
            float v[4] = {acc[mf][nf][0], acc[mf][nf][1], acc[mf][nf][2], acc[mf][nf][3]};
            if (mode == 1 || mode == 3) {
                #pragma unroll
                for (int u = 0; u < 4; u++) v[u] = __uint_as_float(f2tf(v[u]));
            } else if (mode == 2) {
                #pragma unroll
                for (int u = 0; u < 4; u++) v[u] = __uint_as_float(f2tf(v[u] * QSC));
            }
            if (mode == 3) {
                #pragma unroll
                for (int rw = 0; rw < 2; rw++) {
                    const int rr = r + rw * 8;
                    const int bb = rr >> 11, key = rr & 2047;
                    #pragma unroll
                    for (int cc = 0; cc < 2; cc++) {
                        const int col = c + cc;
                        C[(((size_t)bb * H_ + (col >> 6)) * HD_ + (col & 63)) * NK + key]
                            = v[rw * 2 + cc];
                    }
                }
            } else {
                *(float2*)&C[(size_t)r * N + c]       = make_float2(v[0], v[1]);
                *(float2*)&C[(size_t)(r + 8) * N + c] = make_float2(v[2], v[3]);
            }
        }
}

#define QKV_SMEM (3 * (128 * 20 + 16 * 136) * 4)
#define OUT_SMEM (3 * (64 * 20 + 16 * 72) * 4)

__global__ __launch_bounds__(256, 2) void gemm_qkv_kernel()
{
    extern __shared__ float gsm[];
    int by = blockIdx.y;
    const float *A, *Bw; float* C; int mode;
    if (by < 16)      { A = g_QinT; Bw = g_WqT; C = g_Q; mode = 2; }
    else if (by < 48) { A = g_KvT;  Bw = g_WkT; C = g_K; mode = 1; by -= 16; }
    else              { A = g_KvT;  Bw = g_WvT; C = g_V; mode = 3; by -= 48; }
    gemm_raw_body<128, 128>(A, Bw, C, HID_, DIM_, by * 128, mode, gsm);
}

__global__ __launch_bounds__(256, 3) void gemm_out_kernel(float* __restrict__ out)
{
    extern __shared__ float gsm[];
    gemm_raw_body<64, 64>(g_attn, g_WoT, out, DIM_, HID_, blockIdx.y * 64, 0, gsm);
}

// ---------------------------------------------------------------------------
// TF32 flash attention, CTA split-K(2), no-max softmax, full-LDSM fragments.
// CTA = 64 q x 1024 keys, 128 thr / 4 warps, 32-key tiles, 4 CTAs/SM.
// ext (d^2 operand) streamed from g_ext via cp.async in the K commit group.
// ---------------------------------------------------------------------------
#define AKT    32
#define KV_STR 76
#define VT_STR 36
#define P_STR  36
#define KBUF   (AKT * KV_STR)
#define VBUF   (HD_ * VT_STR)
#define OFF_K   0                        // 2*2432 = 4864
#define OFF_V   4864                     // 2*2304 = 4608
#define OFF_P   9472                     // 64*36  = 2304
#define OFF_LUT 11776                    // 1024 float2 = 2048 words
#define ATT_SMEM_FLOATS 13824            // 55296 B

__global__ __launch_bounds__(128, 4) void attn_kernel(const float* __restrict__ qc)
{
    extern __shared__ float sm[];
    float2*   slut2 = (float2*)(sm + OFF_LUT);
    uint32_t* Pu    = (uint32_t*)(sm + OFF_P);

    const int b   = blockIdx.z >> 1;
    const int ks  = blockIdx.z & 1;
    const int h   = blockIdx.y;
    const int q0  = blockIdx.x * 64;
    const int tid = threadIdx.x;
    const int lane = tid & 31;
    const int w    = tid >> 5;
    const int lq   = lane >> 2;
    const int lr   = lane & 3;
    const int kstart = ks * (NK / 2);

    {
        const float* lb = g_lut + h * LUT_N;
        for (int i = tid; i < LUT_N - 1; i += 128)
            slut2[i] = make_float2(lb[i], lb[i + 1]);
    }
    const float inv_step2 = g_inv_step2;

    // LDSM lane geometry
    const int k_lane_off  = (lane & 7) * KV_STR + (lane >> 3) * 4;
    const int vt_lane_off = (lane & 7) * VT_STR + (lane >> 3) * 4;
    const uint32_t ext_addr_off = (uint32_t)(lane * KV_STR + 64) * 4;
    const int p_lane_off = (w * 16 + ((lane >> 3) & 1) * 8 + (lane & 7)) * P_STR
                         + (lane >> 4) * 4;

    uint32_t qa[8][4], qa2[4];
    float qn2s0, qn2s1;
    {
        const size_t r0 = ((size_t)(b * NQ + q0 + w * 16 + lq)) * HID_ + h * HD_;
        const size_t r1 = r0 + 8 * HID_;
        #pragma unroll
        for (int kss = 0; kss < 8; kss++) {
            qa[kss][0] = ldr(&g_Q[r0 + kss * 8 + lr]);
            qa[kss][1] = ldr(&g_Q[r1 + kss * 8 + lr]);
            qa[kss][2] = ldr(&g_Q[r0 + kss * 8 + lr + 4]);
            qa[kss][3] = ldr(&g_Q[r1 + kss * 8 + lr + 4]);
        }
        const float* p0 = qc + ((size_t)b * NQ + q0 + w * 16 + lq) * 3;
        const float* p1 = p0 + 8 * 3;
        float c0[4] = {p0[0], p0[1], p0[2], 1.0f};
        float c1[4] = {p1[0], p1[1], p1[2], 1.0f};
        qa2[0] = f2tf(c0[lr]);
        qa2[1] = f2tf(c1[lr]);
        qa2[2] = 0u; qa2[3] = 0u;
        qn2s0 = fmaf(c0[0], c0[0], fmaf(c0[1], c0[1], c0[2] * c0[2])) * inv_step2;
        qn2s1 = fmaf(c1[0], c1[0], fmaf(c1[1], c1[1], c1[2] * c1[2])) * inv_step2;
    }

    float of[8][4] = {};
    float l0 = 0.f, l1 = 0.f;

    const float* Kp  = g_K + ((size_t)b * NK) * HID_ + h * HD_;
    const float* Vpt = g_V + ((size_t)(b * H_ + h) * HD_) * NK;

    const int lkey = tid >> 2;
    const int qo   = (tid & 3) * 16;
    const int vrow = tid >> 1;
    const int vcb  = (tid & 1) * 16;

    auto issue = [&](int t, int bf) {
        const size_t kg = (size_t)(kstart + t * AKT + lkey) * HID_ + qo;
        uint32_t kd = s2u(sm + OFF_K + bf * KBUF + lkey * KV_STR + qo);
        #pragma unroll
        for (int u = 0; u < 4; u++) cpa16(kd + u * 16, Kp + kg + u * 4);
        // ext columns ride along in the same commit group
        if (tid < AKT)
            cpa16(s2u(sm + OFF_K + bf * KBUF + tid * KV_STR + 64),
                  (const float*)(g_ext + (size_t)b * NK + kstart + t * AKT + tid));
        const float* vg = Vpt + (size_t)vrow * NK + kstart + t * AKT + vcb;
        uint32_t vd = s2u(sm + OFF_V + bf * VBUF + vrow * VT_STR + vcb);
        #pragma unroll
        for (int u = 0; u < 4; u++) cpa16(vd + u * 16, vg + u * 4);
        asm volatile("cp.async.commit_group;" ::: "memory");
    };

    issue(0, 0);
    int buf = 0;
    const int NT = (NK / 2) / AKT;
    const uint32_t zero = 0u;

    for (int t = 0; t < NT; t++) {
        const bool more = (t + 1) < NT;
        if (more) {
            issue(t + 1, buf ^ 1);
            asm volatile("cp.async.wait_group 1;" ::: "memory");
        } else {
            asm volatile("cp.async.wait_group 0;" ::: "memory");
        }
        __syncthreads();

        const float* Kb = sm + OFF_K + buf * KBUF;
        const uint32_t kb_s = s2u(Kb);
        const uint32_t vb_s = s2u(sm + OFF_V + buf * VBUF);

        // ---- QK^T via LDSM ----
        float sacc[4][4] = {};
        #pragma unroll
        for (int nf = 0; nf < 4; nf++) {
            const uint32_t kbase = kb_s + (uint32_t)(nf * 8 * KV_STR + k_lane_off) * 4;
            #pragma unroll
            for (int j = 0; j < 4; j++) {
                uint32_t kb[4];
                ldsm4(kb, kbase + j * 64);
                mma8(sacc[nf], qa[2*j],     kb[0], kb[1]);
                mma8(sacc[nf], qa[2*j + 1], kb[2], kb[3]);
            }
        }

        // ---- d^2 ext fragments ----
        uint32_t eb[4];
        ldsm4(eb, kb_s + ext_addr_off);

        // ---- bias + no-max softmax ----
        float ps0 = 0.f, ps1 = 0.f;
        const int prow0 = (w * 16 + lq) * P_STR;
        const int prow1 = prow0 + 8 * P_STR;
        #pragma unroll
        for (int nf = 0; nf < 4; nf++) {
            float dd4[4] = {qn2s0, qn2s0, qn2s1, qn2s1};
            mma8(dd4, qa2, eb[nf], zero);
            float p4[4];
            #pragma unroll
            for (int j = 0; j < 4; j++) {
                float u = dd4[j];
                int ii = (int)u; ii = min(max(ii, 0), LUT_N - 2);
                float fr = u - (float)ii;
                float2 lh = slut2[ii];
                float lg = sacc[nf][j] + fmaf(fr, lh.y - lh.x, lh.x);
                p4[j] = ex2(lg);
            }
            ps0 += p4[0] + p4[1];
            ps1 += p4[2] + p4[3];
            const int c0 = nf * 8 + 2 * lr;
            *(uint2*)&Pu[prow0 + c0] = make_uint2(f2tf(p4[0]), f2tf(p4[1]));
            *(uint2*)&Pu[prow1 + c0] = make_uint2(f2tf(p4[2]), f2tf(p4[3]));
        }
        l0 += ps0;
        l1 += ps1;
        __syncwarp();

        // ---- P V (all fragments via LDSM) ----
        const uint32_t pu_s = s2u(Pu);
        uint32_t pa[4][4];
        #pragma unroll
        for (int kst = 0; kst < 4; kst++)
            ldsm4(pa[kst], pu_s + (uint32_t)(p_lane_off + kst * 8) * 4);
        #pragma unroll
        for (int nf = 0; nf < 8; nf++) {
            const uint32_t vbase = vb_s + (uint32_t)(nf * 8 * VT_STR + vt_lane_off) * 4;
            uint32_t vb0[4], vb1[4];
            ldsm4(vb0, vbase);
            ldsm4(vb1, vbase + 64);
            mma8(of[nf], pa[0], vb0[0], vb0[1]);
            mma8(of[nf], pa[1], vb0[2], vb0[3]);
            mma8(of[nf], pa[2], vb1[0], vb1[1]);
            mma8(of[nf], pa[3], vb1[2], vb1[3]);
        }

        __syncthreads();
        buf ^= 1;
    }

    // epilogue
    float* pO = ks ? g_O2 : g_attn;
    const size_t r0 = ((size_t)(b * NQ + q0 + w * 16 + lq)) * HID_ + h * HD_;
    const size_t r1 = r0 + 8 * HID_;
    #pragma unroll
    for (int nf = 0; nf < 8; nf++) {
        const int c = nf * 8 + 2 * lr;
        *(float2*)&pO[r0 + c] = make_float2(of[nf][0], of[nf][1]);
        *(float2*)&pO[r1 + c] = make_float2(of[nf][2], of[nf][3]);
    }
    l0 += __shfl_xor_sync(0xffffffffu, l0, 1);
    l0 += __shfl_xor_sync(0xffffffffu, l0, 2);
    l1 += __shfl_xor_sync(0xffffffffu, l1, 1);
    l1 += __shfl_xor_sync(0xffffffffu, l1, 2);
    if (lr == 0) {
        const size_t base = (((size_t)ks * B_ + b) * H_ + h) * NQ;
        const int qr = q0 + w * 16 + lq;
        g_l[base + qr]     = l0;
        g_l[base + qr + 8] = l1;
    }
}

// ---------------------------------------------------------------------------
__global__ __launch_bounds__(512) void merge_kernel()
{
    const int row = blockIdx.x;
    const int b = row >> 10;
    const int q = row & 1023;
    const int c = threadIdx.x;
    const int h = c >> 6;

    const float lA = g_l[(((size_t)0 * B_ + b) * H_ + h) * NQ + q];
    const float lB = g_l[(((size_t)1 * B_ + b) * H_ + h) * NQ + q];
    const float inv = __fdividef(1.f, lA + lB);

    const size_t o = (size_t)row * HID_ + c;
    g_attn[o] = __uint_as_float(f2tf((g_attn[o] + g_O2[o]) * inv));
}

// ---------------------------------------------------------------------------
extern "C" void kernel_launch(void* const* d_in, const int* in_sizes, int n_in,
                              void* d_out, int out_size)
{
    const float* q_in      = (const float*)d_in[0];
    const float* kv_in     = (const float*)d_in[1];
    const float* q_coords  = (const float*)d_in[2];
    const float* kv_coords = (const float*)d_in[3];
    const float* Wq        = (const float*)d_in[4];
    const float* Wk        = (const float*)d_in[5];
    const float* Wv        = (const float*)d_in[6];
    const float* Wo        = (const float*)d_in[7];
    const float* W1        = (const float*)d_in[8];
    const float* b1        = (const float*)d_in[9];
    const float* W2        = (const float*)d_in[10];
    const float* b2        = (const float*)d_in[11];
    float* out             = (float*)d_out;

    static bool attr_set = false;
    if (!attr_set) {
        cudaFuncSetAttribute(attn_kernel,
            cudaFuncAttributeMaxDynamicSharedMemorySize, ATT_SMEM_FLOATS * 4);
        cudaFuncSetAttribute(gemm_qkv_kernel,
            cudaFuncAttributeMaxDynamicSharedMemorySize, QKV_SMEM);
        cudaFuncSetAttribute(gemm_out_kernel,
            cudaFuncAttributeMaxDynamicSharedMemorySize, OUT_SMEM);
        attr_set = true;
    }

    conv_kernel<<<4096, 256>>>((const float4*)q_in, (const float4*)kv_in,
                               (const float4*)Wq, (const float4*)Wk,
                               (const float4*)Wv, (const float4*)Wo,
                               q_coords, kv_coords);
    // blocks 0-3: per-head LUT; blocks 4-19: g_ext table
    lut_kernel<<<20, 256>>>(W1, b1, W2, b2, kv_coords);

    gemm_qkv_kernel<<<dim3(HID_ / 128, 80), 256, QKV_SMEM>>>();

    attn_kernel<<<dim3(NQ / 64, H_, B_ * 2), 128, ATT_SMEM_FLOATS * 4>>>(q_coords);

    merge_kernel<<<B_ * NQ, 512>>>();

    gemm_out_kernel<<<dim3(DIM_ / 64, (B_ * NQ) / 64), 256, OUT_SMEM>>>(out);
}

// round 13
// speedup vs baseline: 1.8092x; 1.7939x over previous
#include <cuda_runtime.h>
#include <cuda_fp16.h>
#include <math.h>
#include <stdint.h>

#define B_    2
#define NQ    1024
#define NK    2048
#define DIM_  512
#define HID_  512
#define H_    8
#define HD_   64
#define RBH   64
#define LUT_N 1024
#define LOG2E 1.4426950408889634f
#define QSC   (0.125f * LOG2E)

// fp16 tensors
__device__ __half g_Qh[(size_t)B_ * NQ * HID_];     // pre-scaled by QSC
__device__ __half g_Kh[(size_t)B_ * NK * HID_];
__device__ __half g_Vh[(size_t)B_ * H_ * HD_ * NK]; // TRANSPOSED [b][h][d][key]
__device__ __half g_attnh[(size_t)B_ * NQ * HID_];  // merged attention out
// fp32 partials + softmax denoms
__device__ float g_attn[(size_t)B_ * NQ * HID_];
__device__ float g_O2[(size_t)B_ * NQ * HID_];
__device__ float g_l[2 * B_ * H_ * NQ];
// bias machinery
__device__ float g_lut[H_ * LUT_N];                 // bias(d^2) * log2e
__device__ float4 g_ext[B_ * NK];                   // tf32-pattern d^2 operand
__device__ unsigned int g_maxbits[2] = {0u, 0u};
__device__ float g_inv_step2;
// fp16 copies of harness inputs
__device__ __half g_QinH[(size_t)B_ * NQ * DIM_];
__device__ __half g_KvH[(size_t)B_ * NK * DIM_];
__device__ __half g_WqH[DIM_ * HID_];
__device__ __half g_WkH[DIM_ * HID_];
__device__ __half g_WvH[DIM_ * HID_];
__device__ __half g_WoH[HID_ * DIM_];

// ---------------------------------------------------------------------------
__device__ __forceinline__ uint32_t f2tf(float x) {
    uint32_t r; asm("cvt.rna.tf32.f32 %0, %1;" : "=r"(r) : "f"(x)); return r;
}
__device__ __forceinline__ uint32_t pk2h(float lo, float hi) {  // {lo,hi} fp16x2
    uint32_t r; asm("cvt.rn.f16x2.f32 %0, %1, %2;" : "=r"(r) : "f"(hi), "f"(lo)); return r;
}
__device__ __forceinline__ float ex2(float x) {
    float y; asm("ex2.approx.f32 %0, %1;" : "=f"(y) : "f"(x)); return y;
}
__device__ __forceinline__ void mma16(float* d, const uint32_t* a, uint32_t b0, uint32_t b1) {
    asm("mma.sync.aligned.m16n8k16.row.col.f32.f16.f16.f32 "
        "{%0,%1,%2,%3}, {%4,%5,%6,%7}, {%8,%9}, {%0,%1,%2,%3};"
        : "+f"(d[0]), "+f"(d[1]), "+f"(d[2]), "+f"(d[3])
        : "r"(a[0]), "r"(a[1]), "r"(a[2]), "r"(a[3]), "r"(b0), "r"(b1));
}
__device__ __forceinline__ void mma8t(float* d, const uint32_t* a, uint32_t b0) {
    asm("mma.sync.aligned.m16n8k8.row.col.f32.tf32.tf32.f32 "
        "{%0,%1,%2,%3}, {%4,%5,%6,%7}, {%8,%9}, {%0,%1,%2,%3};"
        : "+f"(d[0]), "+f"(d[1]), "+f"(d[2]), "+f"(d[3])
        : "r"(a[0]), "r"(a[1]), "r"(a[2]), "r"(a[3]), "r"(b0), "r"(0u));
}
__device__ __forceinline__ void ldsm4(uint32_t* r, uint32_t saddr) {
    asm volatile("ldmatrix.sync.aligned.m8n8.x4.shared.b16 {%0,%1,%2,%3}, [%4];"
        : "=r"(r[0]), "=r"(r[1]), "=r"(r[2]), "=r"(r[3]) : "r"(saddr));
}
__device__ __forceinline__ void ldsm4t(uint32_t* r, uint32_t saddr) {
    asm volatile("ldmatrix.sync.aligned.m8n8.x4.trans.shared.b16 {%0,%1,%2,%3}, [%4];"
        : "=r"(r[0]), "=r"(r[1]), "=r"(r[2]), "=r"(r[3]) : "r"(saddr));
}
__device__ __forceinline__ void cpa16(uint32_t s, const void* g) {
    asm volatile("cp.async.cg.shared.global [%0], [%1], 16;" :: "r"(s), "l"(g));
}
__device__ __forceinline__ uint32_t s2u(const void* p) {
    return (uint32_t)__cvta_generic_to_shared(p);
}

// ---------------------------------------------------------------------------
// conv: fp32 -> fp16 for all matmul operands + coord-norm max
// ---------------------------------------------------------------------------
__global__ __launch_bounds__(256) void conv_kernel(
    const float4* __restrict__ qin, const float4* __restrict__ kvin,
    const float4* __restrict__ wq, const float4* __restrict__ wk,
    const float4* __restrict__ wv, const float4* __restrict__ wo,
    const float* __restrict__ qc, const float* __restrict__ kc)
{
    int i = blockIdx.x * 256 + threadIdx.x;
    float4 v; __half* dst;
    if      (i < 262144) { v = qin[i];            dst = g_QinH + (size_t)i * 4; }
    else if (i < 786432) { v = kvin[i - 262144];  dst = g_KvH + (size_t)(i - 262144) * 4; }
    else if (i < 851968) { v = wq[i - 786432];    dst = g_WqH + (size_t)(i - 786432) * 4; }
    else if (i < 917504) { v = wk[i - 851968];    dst = g_WkH + (size_t)(i - 851968) * 4; }
    else if (i < 983040) { v = wv[i - 917504];    dst = g_WvH + (size_t)(i - 917504) * 4; }
    else                 { v = wo[i - 983040];    dst = g_WoH + (size_t)(i - 983040) * 4; }
    *(uint2*)dst = make_uint2(pk2h(v.x, v.y), pk2h(v.z, v.w));

    const int NQT = B_ * NQ, NKT = B_ * NK;
    if (i < NQT + NKT) {
        float n; int which;
        if (i < NQT) {
            float x = qc[i*3], y = qc[i*3+1], z = qc[i*3+2];
            n = sqrtf(fmaf(x,x,fmaf(y,y,z*z))); which = 0;
        } else {
            int j = i - NQT;
            float x = kc[j*3], y = kc[j*3+1], z = kc[j*3+2];
            n = sqrtf(fmaf(x,x,fmaf(y,y,z*z))); which = 1;
        }
        atomicMax(&g_maxbits[which], __float_as_uint(n));
    }
}

// ---------------------------------------------------------------------------
// lut_kernel: blocks 0-3 per-head LUT; blocks 4-19 ext table
// ---------------------------------------------------------------------------
__global__ __launch_bounds__(256) void lut_kernel(
    const float* __restrict__ W1, const float* __restrict__ b1,
    const float* __restrict__ W2, const float* __restrict__ b2,
    const float* __restrict__ kc)
{
    const int blk = blockIdx.x;
    const int t = threadIdx.x;
    const float dmax = __uint_as_float(g_maxbits[0]) + __uint_as_float(g_maxbits[1]) + 1e-3f;
    const float step2 = dmax * dmax / (float)(LUT_N - 1);
    const float is2 = 1.0f / step2;

    if (blk >= 4) {
        const int j = (blk - 4) * 256 + t;
        const float* p = kc + (size_t)j * 3;
        const float x = p[0], y = p[1], z = p[2];
        float4 e;
        e.x = __uint_as_float(f2tf(-2.f * x * is2));
        e.y = __uint_as_float(f2tf(-2.f * y * is2));
        e.z = __uint_as_float(f2tf(-2.f * z * is2));
        e.w = __uint_as_float(f2tf(fmaf(x, x, fmaf(y, y, z * z)) * is2));
        g_ext[j] = e;
        return;
    }

    __shared__ float sW1[RBH], sb1[RBH], sW2[RBH * H_];
    if (t < RBH) { sW1[t] = W1[t]; sb1[t] = b1[t]; }
    for (int i = t; i < RBH * H_; i += 256) sW2[i] = W2[i];
    __syncthreads();

    if (blk == 0 && t == 0) g_inv_step2 = is2;

    int i = blk * 256 + t;
    if (i >= LUT_N) return;
    float d = sqrtf(step2 * (float)i);

    float o[H_];
    #pragma unroll
    for (int hh = 0; hh < H_; hh++) o[hh] = b2[hh];
    #pragma unroll 8
    for (int j = 0; j < RBH; j++) {
        float x = fmaf(d, sW1[j], sb1[j]);
        float s = __fdividef(x, 1.0f + __expf(-x));
        #pragma unroll
        for (int hh = 0; hh < H_; hh++)
            o[hh] = fmaf(s, sW2[j * H_ + hh], o[hh]);
    }
    #pragma unroll
    for (int hh = 0; hh < H_; hh++)
        g_lut[hh * LUT_N + i] = o[hh] * LOG2E;
}

// ---------------------------------------------------------------------------
// fp16 GEMM body: BMxBN tile, BK=32, 3-stage cp.async, 256 thr, LDSM all frags.
// A stride 40 halves = 80 B (16B-aligned rows, conflict-free ldsm phases).
// mode: 0 fp32 store, 1 fp16, 2 fp16*QSC, 3 fp16 transposed V store.
// ---------------------------------------------------------------------------
#define GASTR 40   // halves

template<int BM, int BN>
__device__ __forceinline__ void gemm_h_body(
    const __half* __restrict__ A, const __half* __restrict__ Bm,
    void* __restrict__ Cp, int N, int K, int row0, int mode, char* sm)
{
    constexpr int BSTR = BN + 8;                  // halves (272B / 144B rows: 16B-mult)
    constexpr int ASZ = BM * GASTR * 2;           // bytes
    constexpr int BSZ = 32 * BSTR * 2;
    constexpr int MF  = BM / 64;
    constexpr int NFW = BN / 16;
    char* As = sm;
    char* Bs = sm + 3 * ASZ;

    const int tid = threadIdx.x;
    const int lane = tid & 31, wid = tid >> 5;
    const int wm = (wid >> 1) * (BM / 4), wn = (wid & 1) * (BN / 2);
    const int col0 = blockIdx.x * BN;
    const int lq = lane >> 2, lr = lane & 3;

    const int ar = (BM == 128) ? (tid >> 1) : (tid >> 2);
    const int ac = (BM == 128) ? ((tid & 1) * 16) : ((tid & 3) * 8);   // halves
    const int bk = tid >> 3;
    const int bn = (tid & 7) * ((BN == 128) ? 16 : 8);                 // halves

    float acc[MF][NFW][4] = {};

    auto issue = [&](int k0) {
        const int st = (k0 >> 5) % 3;
        uint32_t a_s = s2u(As + st * ASZ + (ar * GASTR + ac) * 2);
        const __half* ag = A + (size_t)(row0 + ar) * K + k0 + ac;
        cpa16(a_s, ag);
        if (BM == 128) cpa16(a_s + 16, ag + 8);
        uint32_t b_s = s2u(Bs + st * BSZ + (bk * BSTR + bn) * 2);
        const __half* bg = Bm + (size_t)(k0 + bk) * N + col0 + bn;
        cpa16(b_s, bg);
        if (BN == 128) cpa16(b_s + 16, bg + 8);
        asm volatile("cp.async.commit_group;" ::: "memory");
    };

    issue(0); issue(32);

    // ldsm lane offsets (bytes)
    const int a_lane = (lane & 15) * (GASTR * 2) + (lane >> 4) * 16;
    const int b_lane = ((lane & 7) + ((lane >> 3) & 1) * 8) * (BSTR * 2) + (lane >> 4) * 16;

    for (int k0 = 0; k0 < K; k0 += 32) {
        if (k0 + 64 < K) {
            asm volatile("cp.async.wait_group 1;" ::: "memory");
            __syncthreads();
            issue(k0 + 64);
        } else if (k0 + 32 < K) {
            asm volatile("cp.async.wait_group 1;" ::: "memory");
            __syncthreads();
        } else {
            asm volatile("cp.async.wait_group 0;" ::: "memory");
            __syncthreads();
        }
        const int st = (k0 >> 5) % 3;
        const uint32_t a_b = s2u(As + st * ASZ);
        const uint32_t b_b = s2u(Bs + st * BSZ);

        #pragma unroll
        for (int ks = 0; ks < 2; ks++) {
            uint32_t af[MF][4], bf[NFW / 2][4];
            #pragma unroll
            for (int mf = 0; mf < MF; mf++)
                ldsm4(af[mf], a_b + (wm + mf * 16) * (GASTR * 2) + ks * 32 + a_lane);
            #pragma unroll
            for (int n2 = 0; n2 < NFW / 2; n2++)
                ldsm4t(bf[n2], b_b + ks * 16 * (BSTR * 2) + (wn + n2 * 16) * 2 + b_lane);
            #pragma unroll
            for (int mf = 0; mf < MF; mf++)
                #pragma unroll
                for (int nf = 0; nf < NFW; nf++)
                    mma16(acc[mf][nf], af[mf], bf[nf >> 1][(nf & 1) * 2],
                          bf[nf >> 1][(nf & 1) * 2 + 1]);
        }
        __syncthreads();
    }

    #pragma unroll
    for (int mf = 0; mf < MF; mf++)
        #pragma unroll
        for (int nf = 0; nf < NFW; nf++) {
            const int r = row0 + wm + mf * 16 + lq;
            const int c = col0 + wn + nf * 8 + 2 * lr;
            float* v = acc[mf][nf];
            if (mode == 0) {
                float* C = (float*)Cp;
                *(float2*)&C[(size_t)r * N + c]       = make_float2(v[0], v[1]);
                *(float2*)&C[(size_t)(r + 8) * N + c] = make_float2(v[2], v[3]);
            } else if (mode == 3) {
                __half* C = (__half*)Cp;
                #pragma unroll
                for (int rw = 0; rw < 2; rw++) {
                    const int rr = r + rw * 8;
                    const int bb = rr >> 11, key = rr & 2047;
                    #pragma unroll
                    for (int cc = 0; cc < 2; cc++) {
                        const int col = c + cc;
                        C[(((size_t)bb * H_ + (col >> 6)) * HD_ + (col & 63)) * NK + key]
                            = __float2half_rn(v[rw * 2 + cc]);
                    }
                }
            } else {
                const float s = (mode == 2) ? QSC : 1.0f;
                __half* C = (__half*)Cp;
                *(uint32_t*)&C[(size_t)r * N + c]       = pk2h(v[0] * s, v[1] * s);
                *(uint32_t*)&C[(size_t)(r + 8) * N + c] = pk2h(v[2] * s, v[3] * s);
            }
        }
}

#define QKV_SMEM (3 * (128 * GASTR * 2 + 32 * 136 * 2))
#define OUT_SMEM (3 * (64 * GASTR * 2 + 32 * 72 * 2))

__global__ __launch_bounds__(256, 2) void gemm_qkv_kernel()
{
    extern __shared__ char gsm[];
    int by = blockIdx.y;
    const __half *A, *Bw; void* C; int mode;
    if (by < 16)      { A = g_QinH; Bw = g_WqH; C = g_Qh; mode = 2; }
    else if (by < 48) { A = g_KvH;  Bw = g_WkH; C = g_Kh; mode = 1; by -= 16; }
    else              { A = g_KvH;  Bw = g_WvH; C = g_Vh; mode = 3; by -= 48; }
    gemm_h_body<128, 128>(A, Bw, C, HID_, DIM_, by * 128, mode, gsm);
}

__global__ __launch_bounds__(256, 3) void gemm_out_kernel(float* __restrict__ out)
{
    extern __shared__ char gsm[];
    gemm_h_body<64, 64>(g_attnh, g_WoH, out, DIM_, HID_, blockIdx.y * 64, 0, gsm);
}

// ---------------------------------------------------------------------------
// fp16 flash attention, CTA split-K(2), no-max softmax, full-LDSM fragments.
// CTA = 64 q x 1024 keys, 128 thr / 4 warps, 32-key tiles, 4 CTAs/SM.
// d^2 bias via tf32 ext mma.
// ---------------------------------------------------------------------------
#define AKT    32
#define KSTRH  72    // K tile halves/row (144 B: 16B-mult, phase r*4 distinct)
#define VSTRH  40    // V^T tile halves/row (80 B: 16B-mult, phase r*20 distinct)
#define PSTRH  40    // P halves/row
#define KBUFB  (AKT * KSTRH * 2)          // 4608 B
#define VBUFB  (HD_ * VSTRH * 2)          // 5120 B
// byte offsets
#define OFF_K   0                         // 2 * 4608 = 9216
#define OFF_EXT 9216                      // 2 * 512 = 1024
#define OFF_V   10240                     // 2 * 5120 = 10240
#define OFF_P   20480                     // 64*40*2 = 5120
#define OFF_LUT 25600                     // 1024 * 8 = 8192
#define ATT_SMEM_BYTES 33792

__global__ __launch_bounds__(128, 4) void attn_kernel(const float* __restrict__ qc)
{
    extern __shared__ char smc[];
    float2* slut2 = (float2*)(smc + OFF_LUT);
    __half* Ph    = (__half*)(smc + OFF_P);

    const int b   = blockIdx.z >> 1;
    const int ks_ = blockIdx.z & 1;
    const int h   = blockIdx.y;
    const int q0  = blockIdx.x * 64;
    const int tid = threadIdx.x;
    const int lane = tid & 31;
    const int w    = tid >> 5;
    const int lq   = lane >> 2;
    const int lr   = lane & 3;
    const int kstart = ks_ * (NK / 2);

    {
        const float* lb = g_lut + h * LUT_N;
        for (int i = tid; i < LUT_N - 1; i += 128)
            slut2[i] = make_float2(lb[i], lb[i + 1]);
    }
    const float inv_step2 = g_inv_step2;

    // ldsm lane offsets (bytes)
    const int k_lane = (lane & 7) * (KSTRH * 2) + (lane >> 3) * 16;
    const int v_lane = (lane & 7) * (VSTRH * 2) + (lane >> 3) * 16;
    const int p_lane = (w * 16 + (lane & 15)) * (PSTRH * 2) + (lane >> 4) * 16;
    const int e_lane = lane * 16;

    // Q fragments: fp16 pairs straight from gmem
    uint32_t qa[4][4], qa2[4];
    float qn2s0, qn2s1;
    {
        const size_t r0 = ((size_t)(b * NQ + q0 + w * 16 + lq)) * HID_ + h * HD_;
        const size_t r1 = r0 + 8 * HID_;
        #pragma unroll
        for (int ks = 0; ks < 4; ks++) {
            qa[ks][0] = *(const uint32_t*)&g_Qh[r0 + ks * 16 + 2 * lr];
            qa[ks][1] = *(const uint32_t*)&g_Qh[r1 + ks * 16 + 2 * lr];
            qa[ks][2] = *(const uint32_t*)&g_Qh[r0 + ks * 16 + 2 * lr + 8];
            qa[ks][3] = *(const uint32_t*)&g_Qh[r1 + ks * 16 + 2 * lr + 8];
        }
        const float* p0 = qc + ((size_t)b * NQ + q0 + w * 16 + lq) * 3;
        const float* p1 = p0 + 8 * 3;
        float c0[4] = {p0[0], p0[1], p0[2], 1.0f};
        float c1[4] = {p1[0], p1[1], p1[2], 1.0f};
        qa2[0] = f2tf(c0[lr]);
        qa2[1] = f2tf(c1[lr]);
        qa2[2] = 0u; qa2[3] = 0u;
        qn2s0 = fmaf(c0[0], c0[0], fmaf(c0[1], c0[1], c0[2] * c0[2])) * inv_step2;
        qn2s1 = fmaf(c1[0], c1[0], fmaf(c1[1], c1[1], c1[2] * c1[2])) * inv_step2;
    }

    float of[8][4] = {};
    float l0 = 0.f, l1 = 0.f;

    const __half* Kp  = g_Kh + ((size_t)b * NK) * HID_ + h * HD_;
    const __half* Vpt = g_Vh + ((size_t)(b * H_ + h) * HD_) * NK;

    const int lkey = tid >> 2;            // K loader: key row, 4 thr x 32B
    const int qo   = (tid & 3) * 16;      // halves
    const int vrow = tid >> 1;            // V loader: d row, 2 thr x 32B
    const int vcb  = (tid & 1) * 16;      // halves

    auto issue = [&](int t, int bf) {
        const __half* kg = Kp + (size_t)(kstart + t * AKT + lkey) * HID_ + qo;
        uint32_t kd = s2u(smc + OFF_K + bf * KBUFB + (lkey * KSTRH + qo) * 2);
        cpa16(kd, kg); cpa16(kd + 16, kg + 8);
        if (tid < AKT)
            cpa16(s2u(smc + OFF_EXT + bf * 512 + tid * 16),
                  g_ext + (size_t)b * NK + kstart + t * AKT + tid);
        const __half* vg = Vpt + (size_t)vrow * NK + kstart + t * AKT + vcb;
        uint32_t vd = s2u(smc + OFF_V + bf * VBUFB + (vrow * VSTRH + vcb) * 2);
        cpa16(vd, vg); cpa16(vd + 16, vg + 8);
        asm volatile("cp.async.commit_group;" ::: "memory");
    };

    issue(0, 0);
    int buf = 0;
    const int NT = (NK / 2) / AKT;

    for (int t = 0; t < NT; t++) {
        const bool more = (t + 1) < NT;
        if (more) {
            issue(t + 1, buf ^ 1);
            asm volatile("cp.async.wait_group 1;" ::: "memory");
        } else {
            asm volatile("cp.async.wait_group 0;" ::: "memory");
        }
        __syncthreads();

        const uint32_t kb_s = s2u(smc + OFF_K + buf * KBUFB);
        const uint32_t eb_s = s2u(smc + OFF_EXT + buf * 512);
        const uint32_t vb_s = s2u(smc + OFF_V + buf * VBUFB);

        // ---- QK^T (fp16 k16 mma) ----
        float sacc[4][4] = {};
        #pragma unroll
        for (int nf = 0; nf < 4; nf++) {
            const uint32_t kbase = kb_s + nf * 8 * (KSTRH * 2) + k_lane;
            uint32_t kb[4];
            ldsm4(kb, kbase);
            mma16(sacc[nf], qa[0], kb[0], kb[1]);
            mma16(sacc[nf], qa[1], kb[2], kb[3]);
            ldsm4(kb, kbase + 64);
            mma16(sacc[nf], qa[2], kb[0], kb[1]);
            mma16(sacc[nf], qa[3], kb[2], kb[3]);
        }

        // ---- d^2 ext fragments (tf32 path) ----
        uint32_t eb[4];
        ldsm4(eb, eb_s + e_lane);

        // ---- bias + no-max softmax ----
        float ps0 = 0.f, ps1 = 0.f;
        const int prow0 = (w * 16 + lq) * PSTRH;
        const int prow1 = prow0 + 8 * PSTRH;
        #pragma unroll
        for (int nf = 0; nf < 4; nf++) {
            float dd4[4] = {qn2s0, qn2s0, qn2s1, qn2s1};
            mma8t(dd4, qa2, eb[nf]);
            float p4[4];
            #pragma unroll
            for (int j = 0; j < 4; j++) {
                float u = dd4[j];
                int ii = (int)u; ii = min(max(ii, 0), LUT_N - 2);
                float fr = u - (float)ii;
                float2 lh = slut2[ii];
                float lg = sacc[nf][j] + fmaf(fr, lh.y - lh.x, lh.x);
                p4[j] = ex2(lg);
            }
            ps0 += p4[0] + p4[1];
            ps1 += p4[2] + p4[3];
            const int c0 = nf * 8 + 2 * lr;
            *(uint32_t*)&Ph[prow0 + c0] = pk2h(p4[0], p4[1]);
            *(uint32_t*)&Ph[prow1 + c0] = pk2h(p4[2], p4[3]);
        }
        l0 += ps0;
        l1 += ps1;
        __syncwarp();

        // ---- P V (fp16, all LDSM) ----
        const uint32_t pu_s = s2u(Ph);
        uint32_t pa0[4], pa1[4];
        ldsm4(pa0, pu_s + p_lane);
        ldsm4(pa1, pu_s + p_lane + 32);
        #pragma unroll
        for (int nf = 0; nf < 8; nf++) {
            uint32_t vb[4];
            ldsm4(vb, vb_s + nf * 8 * (VSTRH * 2) + v_lane);
            mma16(of[nf], pa0, vb[0], vb[1]);
            mma16(of[nf], pa1, vb[2], vb[3]);
        }

        __syncthreads();
        buf ^= 1;
    }

    // epilogue: unnormalized fp32 partial + l
    float* pO = ks_ ? g_O2 : g_attn;
    const size_t r0 = ((size_t)(b * NQ + q0 + w * 16 + lq)) * HID_ + h * HD_;
    const size_t r1 = r0 + 8 * HID_;
    #pragma unroll
    for (int nf = 0; nf < 8; nf++) {
        const int c = nf * 8 + 2 * lr;
        *(float2*)&pO[r0 + c] = make_float2(of[nf][0], of[nf][1]);
        *(float2*)&pO[r1 + c] = make_float2(of[nf][2], of[nf][3]);
    }
    l0 += __shfl_xor_sync(0xffffffffu, l0, 1);
    l0 += __shfl_xor_sync(0xffffffffu, l0, 2);
    l1 += __shfl_xor_sync(0xffffffffu, l1, 1);
    l1 += __shfl_xor_sync(0xffffffffu, l1, 2);
    if (lr == 0) {
        const size_t base = (((size_t)ks_ * B_ + b) * H_ + h) * NQ;
        const int qr = q0 + w * 16 + lq;
        g_l[base + qr]     = l0;
        g_l[base + qr + 8] = l1;
    }
}

// ---------------------------------------------------------------------------
__global__ __launch_bounds__(512) void merge_kernel()
{
    const int row = blockIdx.x;
    const int b = row >> 10;
    const int q = row & 1023;
    const int c = threadIdx.x;
    const int h = c >> 6;

    const float lA = g_l[(((size_t)0 * B_ + b) * H_ + h) * NQ + q];
    const float lB = g_l[(((size_t)1 * B_ + b) * H_ + h) * NQ + q];
    const float inv = __fdividef(1.f, lA + lB);

    const size_t o = (size_t)row * HID_ + c;
    g_attnh[o] = __float2half_rn((g_attn[o] + g_O2[o]) * inv);
}

// ---------------------------------------------------------------------------
extern "C" void kernel_launch(void* const* d_in, const int* in_sizes, int n_in,
                              void* d_out, int out_size)
{
    const float* q_in      = (const float*)d_in[0];
    const float* kv_in     = (const float*)d_in[1];
    const float* q_coords  = (const float*)d_in[2];
    const float* kv_coords = (const float*)d_in[3];
    const float* Wq        = (const float*)d_in[4];
    const float* Wk        = (const float*)d_in[5];
    const float* Wv        = (const float*)d_in[6];
    const float* Wo        = (const float*)d_in[7];
    const float* W1        = (const float*)d_in[8];
    const float* b1        = (const float*)d_in[9];
    const float* W2        = (const float*)d_in[10];
    const float* b2        = (const float*)d_in[11];
    float* out             = (float*)d_out;

    static bool attr_set = false;
    if (!attr_set) {
        cudaFuncSetAttribute(attn_kernel,
            cudaFuncAttributeMaxDynamicSharedMemorySize, ATT_SMEM_BYTES);
        cudaFuncSetAttribute(gemm_qkv_kernel,
            cudaFuncAttributeMaxDynamicSharedMemorySize, QKV_SMEM);
        cudaFuncSetAttribute(gemm_out_kernel,
            cudaFuncAttributeMaxDynamicSharedMemorySize, OUT_SMEM);
        attr_set = true;
    }

    conv_kernel<<<4096, 256>>>((const float4*)q_in, (const float4*)kv_in,
                               (const float4*)Wq, (const float4*)Wk,
                               (const float4*)Wv, (const float4*)Wo,
                               q_coords, kv_coords);
    lut_kernel<<<20, 256>>>(W1, b1, W2, b2, kv_coords);

    gemm_qkv_kernel<<<dim3(HID_ / 128, 80), 256, QKV_SMEM>>>();

    attn_kernel<<<dim3(NQ / 64, H_, B_ * 2), 128, ATT_SMEM_BYTES>>>(q_coords);

    merge_kernel<<<B_ * NQ, 512>>>();

    gemm_out_kernel<<<dim3(DIM_ / 64, (B_ * NQ) / 64), 256, OUT_SMEM>>>(out);
}

// round 14
// speedup vs baseline: 1.9059x; 1.0534x over previous
#include <cuda_runtime.h>
#include <cuda_fp16.h>
#include <math.h>
#include <stdint.h>

#define B_    2
#define NQ    1024
#define NK    2048
#define DIM_  512
#define HID_  512
#define H_    8
#define HD_   64
#define RBH   64
#define LUT_N 1024
#define LOG2E 1.4426950408889634f
#define QSC   (0.125f * LOG2E)

// fp16 tensors
__device__ __half g_Qh[(size_t)B_ * NQ * HID_];     // pre-scaled by QSC
__device__ __half g_Kh[(size_t)B_ * NK * HID_];
__device__ __half g_Vh[(size_t)B_ * H_ * HD_ * NK]; // TRANSPOSED [b][h][d][key]
__device__ __half g_attnh[(size_t)B_ * NQ * HID_];  // merged attention out
// fp32 partials + softmax denoms
__device__ float g_attn[(size_t)B_ * NQ * HID_];
__device__ float g_O2[(size_t)B_ * NQ * HID_];
__device__ float g_l[2 * B_ * H_ * NQ];
// bias machinery
__device__ float g_lut[H_ * LUT_N];                 // bias(d^2) * log2e
__device__ float4 g_ext[B_ * NK];                   // tf32-pattern d^2 operand
__device__ unsigned int g_maxbits[2] = {0u, 0u};
__device__ float g_inv_step2;
// fp16 copies of harness inputs
__device__ __half g_QinH[(size_t)B_ * NQ * DIM_];
__device__ __half g_KvH[(size_t)B_ * NK * DIM_];
__device__ __half g_WqH[DIM_ * HID_];
__device__ __half g_WkH[DIM_ * HID_];
__device__ __half g_WvH[DIM_ * HID_];
__device__ __half g_WoH[HID_ * DIM_];

// ---------------------------------------------------------------------------
__device__ __forceinline__ uint32_t f2tf(float x) {
    uint32_t r; asm("cvt.rna.tf32.f32 %0, %1;" : "=r"(r) : "f"(x)); return r;
}
__device__ __forceinline__ uint32_t pk2h(float lo, float hi) {  // {lo,hi} fp16x2
    uint32_t r; asm("cvt.rn.f16x2.f32 %0, %1, %2;" : "=r"(r) : "f"(hi), "f"(lo)); return r;
}
__device__ __forceinline__ float ex2(float x) {
    float y; asm("ex2.approx.f32 %0, %1;" : "=f"(y) : "f"(x)); return y;
}
__device__ __forceinline__ void mma16(float* d, const uint32_t* a, uint32_t b0, uint32_t b1) {
    asm("mma.sync.aligned.m16n8k16.row.col.f32.f16.f16.f32 "
        "{%0,%1,%2,%3}, {%4,%5,%6,%7}, {%8,%9}, {%0,%1,%2,%3};"
        : "+f"(d[0]), "+f"(d[1]), "+f"(d[2]), "+f"(d[3])
        : "r"(a[0]), "r"(a[1]), "r"(a[2]), "r"(a[3]), "r"(b0), "r"(b1));
}
__device__ __forceinline__ void mma8t(float* d, const uint32_t* a, uint32_t b0) {
    asm("mma.sync.aligned.m16n8k8.row.col.f32.tf32.tf32.f32 "
        "{%0,%1,%2,%3}, {%4,%5,%6,%7}, {%8,%9}, {%0,%1,%2,%3};"
        : "+f"(d[0]), "+f"(d[1]), "+f"(d[2]), "+f"(d[3])
        : "r"(a[0]), "r"(a[1]), "r"(a[2]), "r"(a[3]), "r"(b0), "r"(0u));
}
__device__ __forceinline__ void ldsm4(uint32_t* r, uint32_t saddr) {
    asm volatile("ldmatrix.sync.aligned.m8n8.x4.shared.b16 {%0,%1,%2,%3}, [%4];"
        : "=r"(r[0]), "=r"(r[1]), "=r"(r[2]), "=r"(r[3]) : "r"(saddr));
}
__device__ __forceinline__ void ldsm4t(uint32_t* r, uint32_t saddr) {
    asm volatile("ldmatrix.sync.aligned.m8n8.x4.trans.shared.b16 {%0,%1,%2,%3}, [%4];"
        : "=r"(r[0]), "=r"(r[1]), "=r"(r[2]), "=r"(r[3]) : "r"(saddr));
}
__device__ __forceinline__ void cpa16(uint32_t s, const void* g) {
    asm volatile("cp.async.cg.shared.global [%0], [%1], 16;" :: "r"(s), "l"(g));
}
__device__ __forceinline__ uint32_t s2u(const void* p) {
    return (uint32_t)__cvta_generic_to_shared(p);
}

// ---------------------------------------------------------------------------
// conv: fp32 -> fp16 for all matmul operands + coord-norm max
// ---------------------------------------------------------------------------
__global__ __launch_bounds__(256) void conv_kernel(
    const float4* __restrict__ qin, const float4* __restrict__ kvin,
    const float4* __restrict__ wq, const float4* __restrict__ wk,
    const float4* __restrict__ wv, const float4* __restrict__ wo,
    const float* __restrict__ qc, const float* __restrict__ kc)
{
    int i = blockIdx.x * 256 + threadIdx.x;
    float4 v; __half* dst;
    if      (i < 262144) { v = qin[i];            dst = g_QinH + (size_t)i * 4; }
    else if (i < 786432) { v = kvin[i - 262144];  dst = g_KvH + (size_t)(i - 262144) * 4; }
    else if (i < 851968) { v = wq[i - 786432];    dst = g_WqH + (size_t)(i - 786432) * 4; }
    else if (i < 917504) { v = wk[i - 851968];    dst = g_WkH + (size_t)(i - 851968) * 4; }
    else if (i < 983040) { v = wv[i - 917504];    dst = g_WvH + (size_t)(i - 917504) * 4; }
    else                 { v = wo[i - 983040];    dst = g_WoH + (size_t)(i - 983040) * 4; }
    *(uint2*)dst = make_uint2(pk2h(v.x, v.y), pk2h(v.z, v.w));

    const int NQT = B_ * NQ, NKT = B_ * NK;
    if (i < NQT + NKT) {
        float n; int which;
        if (i < NQT) {
            float x = qc[i*3], y = qc[i*3+1], z = qc[i*3+2];
            n = sqrtf(fmaf(x,x,fmaf(y,y,z*z))); which = 0;
        } else {
            int j = i - NQT;
            float x = kc[j*3], y = kc[j*3+1], z = kc[j*3+2];
            n = sqrtf(fmaf(x,x,fmaf(y,y,z*z))); which = 1;
        }
        atomicMax(&g_maxbits[which], __float_as_uint(n));
    }
}

// ---------------------------------------------------------------------------
// lut_kernel: blocks 0-3 per-head LUT; blocks 4-19 ext table
// ---------------------------------------------------------------------------
__global__ __launch_bounds__(256) void lut_kernel(
    const float* __restrict__ W1, const float* __restrict__ b1,
    const float* __restrict__ W2, const float* __restrict__ b2,
    const float* __restrict__ kc)
{
    const int blk = blockIdx.x;
    const int t = threadIdx.x;
    const float dmax = __uint_as_float(g_maxbits[0]) + __uint_as_float(g_maxbits[1]) + 1e-3f;
    const float step2 = dmax * dmax / (float)(LUT_N - 1);
    const float is2 = 1.0f / step2;

    if (blk >= 4) {
        const int j = (blk - 4) * 256 + t;
        const float* p = kc + (size_t)j * 3;
        const float x = p[0], y = p[1], z = p[2];
        float4 e;
        e.x = __uint_as_float(f2tf(-2.f * x * is2));
        e.y = __uint_as_float(f2tf(-2.f * y * is2));
        e.z = __uint_as_float(f2tf(-2.f * z * is2));
        e.w = __uint_as_float(f2tf(fmaf(x, x, fmaf(y, y, z * z)) * is2));
        g_ext[j] = e;
        return;
    }

    __shared__ float sW1[RBH], sb1[RBH], sW2[RBH * H_];
    if (t < RBH) { sW1[t] = W1[t]; sb1[t] = b1[t]; }
    for (int i = t; i < RBH * H_; i += 256) sW2[i] = W2[i];
    __syncthreads();

    if (blk == 0 && t == 0) g_inv_step2 = is2;

    int i = blk * 256 + t;
    if (i >= LUT_N) return;
    float d = sqrtf(step2 * (float)i);

    float o[H_];
    #pragma unroll
    for (int hh = 0; hh < H_; hh++) o[hh] = b2[hh];
    #pragma unroll 8
    for (int j = 0; j < RBH; j++) {
        float x = fmaf(d, sW1[j], sb1[j]);
        float s = __fdividef(x, 1.0f + __expf(-x));
        #pragma unroll
        for (int hh = 0; hh < H_; hh++)
            o[hh] = fmaf(s, sW2[j * H_ + hh], o[hh]);
    }
    #pragma unroll
    for (int hh = 0; hh < H_; hh++)
        g_lut[hh * LUT_N + i] = o[hh] * LOG2E;
}

// ---------------------------------------------------------------------------
// fp16 GEMM body (unchanged from R13): BMxBN, BK=32, 3-stage cp.async, LDSM.
// mode: 0 fp32 store, 1 fp16, 2 fp16*QSC, 3 fp16 transposed V store.
// ---------------------------------------------------------------------------
#define GASTR 40   // halves

template<int BM, int BN>
__device__ __forceinline__ void gemm_h_body(
    const __half* __restrict__ A, const __half* __restrict__ Bm,
    void* __restrict__ Cp, int N, int K, int row0, int mode, char* sm)
{
    constexpr int BSTR = BN + 8;
    constexpr int ASZ = BM * GASTR * 2;
    constexpr int BSZ = 32 * BSTR * 2;
    constexpr int MF  = BM / 64;
    constexpr int NFW = BN / 16;
    char* As = sm;
    char* Bs = sm + 3 * ASZ;

    const int tid = threadIdx.x;
    const int lane = tid & 31, wid = tid >> 5;
    const int wm = (wid >> 1) * (BM / 4), wn = (wid & 1) * (BN / 2);
    const int col0 = blockIdx.x * BN;
    const int lq = lane >> 2, lr = lane & 3;

    const int ar = (BM == 128) ? (tid >> 1) : (tid >> 2);
    const int ac = (BM == 128) ? ((tid & 1) * 16) : ((tid & 3) * 8);
    const int bk = tid >> 3;
    const int bn = (tid & 7) * ((BN == 128) ? 16 : 8);

    float acc[MF][NFW][4] = {};

    auto issue = [&](int k0) {
        const int st = (k0 >> 5) % 3;
        uint32_t a_s = s2u(As + st * ASZ + (ar * GASTR + ac) * 2);
        const __half* ag = A + (size_t)(row0 + ar) * K + k0 + ac;
        cpa16(a_s, ag);
        if (BM == 128) cpa16(a_s + 16, ag + 8);
        uint32_t b_s = s2u(Bs + st * BSZ + (bk * BSTR + bn) * 2);
        const __half* bg = Bm + (size_t)(k0 + bk) * N + col0 + bn;
        cpa16(b_s, bg);
        if (BN == 128) cpa16(b_s + 16, bg + 8);
        asm volatile("cp.async.commit_group;" ::: "memory");
    };

    issue(0); issue(32);

    const int a_lane = (lane & 15) * (GASTR * 2) + (lane >> 4) * 16;
    const int b_lane = ((lane & 7) + ((lane >> 3) & 1) * 8) * (BSTR * 2) + (lane >> 4) * 16;

    for (int k0 = 0; k0 < K; k0 += 32) {
        if (k0 + 64 < K) {
            asm volatile("cp.async.wait_group 1;" ::: "memory");
            __syncthreads();
            issue(k0 + 64);
        } else if (k0 + 32 < K) {
            asm volatile("cp.async.wait_group 1;" ::: "memory");
            __syncthreads();
        } else {
            asm volatile("cp.async.wait_group 0;" ::: "memory");
            __syncthreads();
        }
        const int st = (k0 >> 5) % 3;
        const uint32_t a_b = s2u(As + st * ASZ);
        const uint32_t b_b = s2u(Bs + st * BSZ);

        #pragma unroll
        for (int ks = 0; ks < 2; ks++) {
            uint32_t af[MF][4], bf[NFW / 2][4];
            #pragma unroll
            for (int mf = 0; mf < MF; mf++)
                ldsm4(af[mf], a_b + (wm + mf * 16) * (GASTR * 2) + ks * 32 + a_lane);
            #pragma unroll
            for (int n2 = 0; n2 < NFW / 2; n2++)
                ldsm4t(bf[n2], b_b + ks * 16 * (BSTR * 2) + (wn + n2 * 16) * 2 + b_lane);
            #pragma unroll
            for (int mf = 0; mf < MF; mf++)
                #pragma unroll
                for (int nf = 0; nf < NFW; nf++)
                    mma16(acc[mf][nf], af[mf], bf[nf >> 1][(nf & 1) * 2],
                          bf[nf >> 1][(nf & 1) * 2 + 1]);
        }
        __syncthreads();
    }

    #pragma unroll
    for (int mf = 0; mf < MF; mf++)
        #pragma unroll
        for (int nf = 0; nf < NFW; nf++) {
            const int r = row0 + wm + mf * 16 + lq;
            const int c = col0 + wn + nf * 8 + 2 * lr;
            float* v = acc[mf][nf];
            if (mode == 0) {
                float* C = (float*)Cp;
                *(float2*)&C[(size_t)r * N + c]       = make_float2(v[0], v[1]);
                *(float2*)&C[(size_t)(r + 8) * N + c] = make_float2(v[2], v[3]);
            } else if (mode == 3) {
                __half* C = (__half*)Cp;
                #pragma unroll
                for (int rw = 0; rw < 2; rw++) {
                    const int rr = r + rw * 8;
                    const int bb = rr >> 11, key = rr & 2047;
                    #pragma unroll
                    for (int cc = 0; cc < 2; cc++) {
                        const int col = c + cc;
                        C[(((size_t)bb * H_ + (col >> 6)) * HD_ + (col & 63)) * NK + key]
                            = __float2half_rn(v[rw * 2 + cc]);
                    }
                }
            } else {
                const float s = (mode == 2) ? QSC : 1.0f;
                __half* C = (__half*)Cp;
                *(uint32_t*)&C[(size_t)r * N + c]       = pk2h(v[0] * s, v[1] * s);
                *(uint32_t*)&C[(size_t)(r + 8) * N + c] = pk2h(v[2] * s, v[3] * s);
            }
        }
}

#define QKV_SMEM (3 * (128 * GASTR * 2 + 32 * 136 * 2))
#define OUT_SMEM (3 * (64 * GASTR * 2 + 32 * 72 * 2))

__global__ __launch_bounds__(256, 2) void gemm_qkv_kernel()
{
    extern __shared__ char gsm[];
    int by = blockIdx.y;
    const __half *A, *Bw; void* C; int mode;
    if (by < 16)      { A = g_QinH; Bw = g_WqH; C = g_Qh; mode = 2; }
    else if (by < 48) { A = g_KvH;  Bw = g_WkH; C = g_Kh; mode = 1; by -= 16; }
    else              { A = g_KvH;  Bw = g_WvH; C = g_Vh; mode = 3; by -= 48; }
    gemm_h_body<128, 128>(A, Bw, C, HID_, DIM_, by * 128, mode, gsm);
}

__global__ __launch_bounds__(256, 3) void gemm_out_kernel(float* __restrict__ out)
{
    extern __shared__ char gsm[];
    gemm_h_body<64, 64>(g_attnh, g_WoH, out, DIM_, HID_, blockIdx.y * 64, 0, gsm);
}

// ---------------------------------------------------------------------------
// fp16 flash attention: CTA split-K(2), no-max softmax, register-resident P
// (C-frag fp16x2 pack == A-frag layout), half2-packed LUT, 3-stage cp.async
// ring with ONE __syncthreads per tile. 64 q x 1024 keys, 128 thr, 4 CTAs/SM.
// ---------------------------------------------------------------------------
#define AKT    32
#define KSTRH  72    // K tile halves/row (144B rows)
#define VSTRH  40    // V^T tile halves/row (80B rows)
#define KB_    4608  // AKT*KSTRH*2
#define EB_    512
#define VB_    5120  // HD_*VSTRH*2
#define STGB   (KB_ + EB_ + VB_)          // 10240 per stage
#define OFF_LUT (3 * STGB)                // 30720; 1024 uint32 = 4096 B
#define ATT_SMEM_BYTES (3 * STGB + 4096)  // 34816

__global__ __launch_bounds__(128, 4) void attn_kernel(const float* __restrict__ qc)
{
    extern __shared__ char smc[];
    uint32_t* slutp = (uint32_t*)(smc + OFF_LUT);

    const int b   = blockIdx.z >> 1;
    const int ks_ = blockIdx.z & 1;
    const int h   = blockIdx.y;
    const int q0  = blockIdx.x * 64;
    const int tid = threadIdx.x;
    const int lane = tid & 31;
    const int w    = tid >> 5;
    const int lq   = lane >> 2;
    const int lr   = lane & 3;
    const int kstart = ks_ * (NK / 2);

    {   // stage LUT as packed half2 (f[i], f[i+1])
        const float* lb = g_lut + h * LUT_N;
        for (int i = tid; i < LUT_N - 1; i += 128)
            slutp[i] = pk2h(lb[i], lb[i + 1]);
    }
    const float inv_step2 = g_inv_step2;

    // ldsm lane offsets (bytes)
    const int k_lane = (lane & 7) * (KSTRH * 2) + (lane >> 3) * 16;
    const int v_lane = (lane & 7) * (VSTRH * 2) + (lane >> 3) * 16;
    const int e_lane = lane * 16;

    // Q fragments
    uint32_t qa[4][4], qa2[4];
    float qn2s0, qn2s1;
    {
        const size_t r0 = ((size_t)(b * NQ + q0 + w * 16 + lq)) * HID_ + h * HD_;
        const size_t r1 = r0 + 8 * HID_;
        #pragma unroll
        for (int ks = 0; ks < 4; ks++) {
            qa[ks][0] = *(const uint32_t*)&g_Qh[r0 + ks * 16 + 2 * lr];
            qa[ks][1] = *(const uint32_t*)&g_Qh[r1 + ks * 16 + 2 * lr];
            qa[ks][2] = *(const uint32_t*)&g_Qh[r0 + ks * 16 + 2 * lr + 8];
            qa[ks][3] = *(const uint32_t*)&g_Qh[r1 + ks * 16 + 2 * lr + 8];
        }
        const float* p0 = qc + ((size_t)b * NQ + q0 + w * 16 + lq) * 3;
        const float* p1 = p0 + 8 * 3;
        float c0[4] = {p0[0], p0[1], p0[2], 1.0f};
        float c1[4] = {p1[0], p1[1], p1[2], 1.0f};
        qa2[0] = f2tf(c0[lr]);
        qa2[1] = f2tf(c1[lr]);
        qa2[2] = 0u; qa2[3] = 0u;
        qn2s0 = fmaf(c0[0], c0[0], fmaf(c0[1], c0[1], c0[2] * c0[2])) * inv_step2;
        qn2s1 = fmaf(c1[0], c1[0], fmaf(c1[1], c1[1], c1[2] * c1[2])) * inv_step2;
    }

    float of[8][4] = {};
    float l0 = 0.f, l1 = 0.f;

    const __half* Kp  = g_Kh + ((size_t)b * NK) * HID_ + h * HD_;
    const __half* Vpt = g_Vh + ((size_t)(b * H_ + h) * HD_) * NK;

    const int lkey = tid >> 2;            // K loader: key row
    const int qo   = (tid & 3) * 16;      // halves
    const int vrow = tid >> 1;            // V loader: d row
    const int vcb  = (tid & 1) * 16;      // halves

    auto issue = [&](int t) {
        char* stg = smc + (t % 3) * STGB;
        const __half* kg = Kp + (size_t)(kstart + t * AKT + lkey) * HID_ + qo;
        uint32_t kd = s2u(stg + (lkey * KSTRH + qo) * 2);
        cpa16(kd, kg); cpa16(kd + 16, kg + 8);
        if (tid < AKT)
            cpa16(s2u(stg + KB_ + tid * 16),
                  g_ext + (size_t)b * NK + kstart + t * AKT + tid);
        const __half* vg = Vpt + (size_t)vrow * NK + kstart + t * AKT + vcb;
        uint32_t vd = s2u(stg + KB_ + EB_ + (vrow * VSTRH + vcb) * 2);
        cpa16(vd, vg); cpa16(vd + 16, vg + 8);
        asm volatile("cp.async.commit_group;" ::: "memory");
    };

    const int NT = (NK / 2) / AKT;
    issue(0); issue(1);

    for (int t = 0; t < NT; t++) {
        if (t + 1 < NT) {
            asm volatile("cp.async.wait_group 1;" ::: "memory");
        } else {
            asm volatile("cp.async.wait_group 0;" ::: "memory");
        }
        __syncthreads();
        if (t + 2 < NT) issue(t + 2);

        char* stg = smc + (t % 3) * STGB;
        const uint32_t kb_s = s2u(stg);
        const uint32_t eb_s = s2u(stg + KB_);
        const uint32_t vb_s = s2u(stg + KB_ + EB_);

        // ---- QK^T ----
        float sacc[4][4] = {};
        #pragma unroll
        for (int nf = 0; nf < 4; nf++) {
            const uint32_t kbase = kb_s + nf * 8 * (KSTRH * 2) + k_lane;
            uint32_t kb[4];
            ldsm4(kb, kbase);
            mma16(sacc[nf], qa[0], kb[0], kb[1]);
            mma16(sacc[nf], qa[1], kb[2], kb[3]);
            ldsm4(kb, kbase + 64);
            mma16(sacc[nf], qa[2], kb[0], kb[1]);
            mma16(sacc[nf], qa[3], kb[2], kb[3]);
        }

        // ---- d^2 ext fragments ----
        uint32_t eb[4];
        ldsm4(eb, eb_s + e_lane);

        // ---- bias + no-max softmax; pack P directly into A-fragments ----
        uint32_t pa[2][4];
        float ps0 = 0.f, ps1 = 0.f;
        #pragma unroll
        for (int nf = 0; nf < 4; nf++) {
            float dd4[4] = {qn2s0, qn2s0, qn2s1, qn2s1};
            mma8t(dd4, qa2, eb[nf]);
            float p4[4];
            #pragma unroll
            for (int j = 0; j < 4; j++) {
                float u = dd4[j];
                int ii = (int)u; ii = min(max(ii, 0), LUT_N - 2);
                float fr = u - (float)ii;
                uint32_t wL = slutp[ii];
                float2 lf = __half22float2(*(__half2*)&wL);
                float lg = sacc[nf][j] + fmaf(fr, lf.y - lf.x, lf.x);
                p4[j] = ex2(lg);
            }
            ps0 += p4[0] + p4[1];
            ps1 += p4[2] + p4[3];
            pa[nf >> 1][(nf & 1) * 2]     = pk2h(p4[0], p4[1]);
            pa[nf >> 1][(nf & 1) * 2 + 1] = pk2h(p4[2], p4[3]);
        }
        l0 += ps0;
        l1 += ps1;

        // ---- P V (P in registers, V via LDSM) ----
        #pragma unroll
        for (int nf = 0; nf < 8; nf++) {
            uint32_t vb[4];
            ldsm4(vb, vb_s + nf * 8 * (VSTRH * 2) + v_lane);
            mma16(of[nf], pa[0], vb[0], vb[1]);
            mma16(of[nf], pa[1], vb[2], vb[3]);
        }
    }

    // epilogue: unnormalized fp32 partial + l
    float* pO = ks_ ? g_O2 : g_attn;
    const size_t r0 = ((size_t)(b * NQ + q0 + w * 16 + lq)) * HID_ + h * HD_;
    const size_t r1 = r0 + 8 * HID_;
    #pragma unroll
    for (int nf = 0; nf < 8; nf++) {
        const int c = nf * 8 + 2 * lr;
        *(float2*)&pO[r0 + c] = make_float2(of[nf][0], of[nf][1]);
        *(float2*)&pO[r1 + c] = make_float2(of[nf][2], of[nf][3]);
    }
    l0 += __shfl_xor_sync(0xffffffffu, l0, 1);
    l0 += __shfl_xor_sync(0xffffffffu, l0, 2);
    l1 += __shfl_xor_sync(0xffffffffu, l1, 1);
    l1 += __shfl_xor_sync(0xffffffffu, l1, 2);
    if (lr == 0) {
        const size_t base = (((size_t)ks_ * B_ + b) * H_ + h) * NQ;
        const int qr = q0 + w * 16 + lq;
        g_l[base + qr]     = l0;
        g_l[base + qr + 8] = l1;
    }
}

// ---------------------------------------------------------------------------
__global__ __launch_bounds__(512) void merge_kernel()
{
    const int row = blockIdx.x;
    const int b = row >> 10;
    const int q = row & 1023;
    const int c = threadIdx.x;
    const int h = c >> 6;

    const float lA = g_l[(((size_t)0 * B_ + b) * H_ + h) * NQ + q];
    const float lB = g_l[(((size_t)1 * B_ + b) * H_ + h) * NQ + q];
    const float inv = __fdividef(1.f, lA + lB);

    const size_t o = (size_t)row * HID_ + c;
    g_attnh[o] = __float2half_rn((g_attn[o] + g_O2[o]) * inv);
}

// ---------------------------------------------------------------------------
extern "C" void kernel_launch(void* const* d_in, const int* in_sizes, int n_in,
                              void* d_out, int out_size)
{
    const float* q_in      = (const float*)d_in[0];
    const float* kv_in     = (const float*)d_in[1];
    const float* q_coords  = (const float*)d_in[2];
    const float* kv_coords = (const float*)d_in[3];
    const float* Wq        = (const float*)d_in[4];
    const float* Wk        = (const float*)d_in[5];
    const float* Wv        = (const float*)d_in[6];
    const float* Wo        = (const float*)d_in[7];
    const float* W1        = (const float*)d_in[8];
    const float* b1        = (const float*)d_in[9];
    const float* W2        = (const float*)d_in[10];
    const float* b2        = (const float*)d_in[11];
    float* out             = (float*)d_out;

    static bool attr_set = false;
    if (!attr_set) {
        cudaFuncSetAttribute(attn_kernel,
            cudaFuncAttributeMaxDynamicSharedMemorySize, ATT_SMEM_BYTES);
        cudaFuncSetAttribute(gemm_qkv_kernel,
            cudaFuncAttributeMaxDynamicSharedMemorySize, QKV_SMEM);
        cudaFuncSetAttribute(gemm_out_kernel,
            cudaFuncAttributeMaxDynamicSharedMemorySize, OUT_SMEM);
        attr_set = true;
    }

    conv_kernel<<<4096, 256>>>((const float4*)q_in, (const float4*)kv_in,
                               (const float4*)Wq, (const float4*)Wk,
                               (const float4*)Wv, (const float4*)Wo,
                               q_coords, kv_coords);
    lut_kernel<<<20, 256>>>(W1, b1, W2, b2, kv_coords);

    gemm_qkv_kernel<<<dim3(HID_ / 128, 80), 256, QKV_SMEM>>>();

    attn_kernel<<<dim3(NQ / 64, H_, B_ * 2), 128, ATT_SMEM_BYTES>>>(q_coords);

    merge_kernel<<<B_ * NQ, 512>>>();

    gemm_out_kernel<<<dim3(DIM_ / 64, (B_ * NQ) / 64), 256, OUT_SMEM>>>(out);
}

// round 15
// speedup vs baseline: 1.9751x; 1.0363x over previous
#include <cuda_runtime.h>
#include <cuda_fp16.h>
#include <math.h>
#include <stdint.h>

#define B_    2
#define NQ    1024
#define NK    2048
#define DIM_  512
#define HID_  512
#define H_    8
#define HD_   64
#define RBH   64
#define LUT_N 2048
#define LOG2E 1.4426950408889634f
#define QSC   (0.125f * LOG2E)

// fp16 tensors
__device__ __half g_Qh[(size_t)B_ * NQ * HID_];     // pre-scaled by QSC
__device__ __half g_Kh[(size_t)B_ * NK * HID_];
__device__ __half g_Vh[(size_t)B_ * H_ * HD_ * NK]; // TRANSPOSED [b][h][d][key]
__device__ __half g_attnh[(size_t)B_ * NQ * HID_];  // merged attention out
// fp32 partials + softmax denoms
__device__ float g_attn[(size_t)B_ * NQ * HID_];
__device__ float g_O2[(size_t)B_ * NQ * HID_];
__device__ float g_l[2 * B_ * H_ * NQ];
// bias machinery
__device__ float g_lut[H_ * LUT_N];                 // bias(d^2) * log2e
__device__ float4 g_ext[B_ * NK];                   // tf32-pattern d^2 operand
__device__ unsigned int g_maxbits[2] = {0u, 0u};
__device__ float g_inv_step2;
// fp16 copies of harness inputs
__device__ __half g_QinH[(size_t)B_ * NQ * DIM_];
__device__ __half g_KvH[(size_t)B_ * NK * DIM_];
__device__ __half g_WqH[DIM_ * HID_];
__device__ __half g_WkH[DIM_ * HID_];
__device__ __half g_WvH[DIM_ * HID_];
__device__ __half g_WoH[HID_ * DIM_];

// ---------------------------------------------------------------------------
__device__ __forceinline__ uint32_t f2tf(float x) {
    uint32_t r; asm("cvt.rna.tf32.f32 %0, %1;" : "=r"(r) : "f"(x)); return r;
}
__device__ __forceinline__ uint32_t pk2h(float lo, float hi) {  // {lo,hi} fp16x2
    uint32_t r; asm("cvt.rn.f16x2.f32 %0, %1, %2;" : "=r"(r) : "f"(hi), "f"(lo)); return r;
}
__device__ __forceinline__ float ex2(float x) {
    float y; asm("ex2.approx.f32 %0, %1;" : "=f"(y) : "f"(x)); return y;
}
__device__ __forceinline__ void mma16(float* d, const uint32_t* a, uint32_t b0, uint32_t b1) {
    asm("mma.sync.aligned.m16n8k16.row.col.f32.f16.f16.f32 "
        "{%0,%1,%2,%3}, {%4,%5,%6,%7}, {%8,%9}, {%0,%1,%2,%3};"
        : "+f"(d[0]), "+f"(d[1]), "+f"(d[2]), "+f"(d[3])
        : "r"(a[0]), "r"(a[1]), "r"(a[2]), "r"(a[3]), "r"(b0), "r"(b1));
}
__device__ __forceinline__ void mma8t(float* d, const uint32_t* a, uint32_t b0) {
    asm("mma.sync.aligned.m16n8k8.row.col.f32.tf32.tf32.f32 "
        "{%0,%1,%2,%3}, {%4,%5,%6,%7}, {%8,%9}, {%0,%1,%2,%3};"
        : "+f"(d[0]), "+f"(d[1]), "+f"(d[2]), "+f"(d[3])
        : "r"(a[0]), "r"(a[1]), "r"(a[2]), "r"(a[3]), "r"(b0), "r"(0u));
}
__device__ __forceinline__ void ldsm4(uint32_t* r, uint32_t saddr) {
    asm volatile("ldmatrix.sync.aligned.m8n8.x4.shared.b16 {%0,%1,%2,%3}, [%4];"
        : "=r"(r[0]), "=r"(r[1]), "=r"(r[2]), "=r"(r[3]) : "r"(saddr));
}
__device__ __forceinline__ void ldsm4t(uint32_t* r, uint32_t saddr) {
    asm volatile("ldmatrix.sync.aligned.m8n8.x4.trans.shared.b16 {%0,%1,%2,%3}, [%4];"
        : "=r"(r[0]), "=r"(r[1]), "=r"(r[2]), "=r"(r[3]) : "r"(saddr));
}
__device__ __forceinline__ void cpa16(uint32_t s, const void* g) {
    asm volatile("cp.async.cg.shared.global [%0], [%1], 16;" :: "r"(s), "l"(g));
}
__device__ __forceinline__ uint32_t s2u(const void* p) {
    return (uint32_t)__cvta_generic_to_shared(p);
}

// ---------------------------------------------------------------------------
// conv: fp32 -> fp16 for all matmul operands + coord-norm max
// ---------------------------------------------------------------------------
__global__ __launch_bounds__(256) void conv_kernel(
    const float4* __restrict__ qin, const float4* __restrict__ kvin,
    const float4* __restrict__ wq, const float4* __restrict__ wk,
    const float4* __restrict__ wv, const float4* __restrict__ wo,
    const float* __restrict__ qc, const float* __restrict__ kc)
{
    int i = blockIdx.x * 256 + threadIdx.x;
    float4 v; __half* dst;
    if      (i < 262144) { v = qin[i];            dst = g_QinH + (size_t)i * 4; }
    else if (i < 786432) { v = kvin[i - 262144];  dst = g_KvH + (size_t)(i - 262144) * 4; }
    else if (i < 851968) { v = wq[i - 786432];    dst = g_WqH + (size_t)(i - 786432) * 4; }
    else if (i < 917504) { v = wk[i - 851968];    dst = g_WkH + (size_t)(i - 851968) * 4; }
    else if (i < 983040) { v = wv[i - 917504];    dst = g_WvH + (size_t)(i - 917504) * 4; }
    else                 { v = wo[i - 983040];    dst = g_WoH + (size_t)(i - 983040) * 4; }
    *(uint2*)dst = make_uint2(pk2h(v.x, v.y), pk2h(v.z, v.w));

    const int NQT = B_ * NQ, NKT = B_ * NK;
    if (i < NQT + NKT) {
        float n; int which;
        if (i < NQT) {
            float x = qc[i*3], y = qc[i*3+1], z = qc[i*3+2];
            n = sqrtf(fmaf(x,x,fmaf(y,y,z*z))); which = 0;
        } else {
            int j = i - NQT;
            float x = kc[j*3], y = kc[j*3+1], z = kc[j*3+2];
            n = sqrtf(fmaf(x,x,fmaf(y,y,z*z))); which = 1;
        }
        atomicMax(&g_maxbits[which], __float_as_uint(n));
    }
}

// ---------------------------------------------------------------------------
// lut_kernel: blocks 0-7 per-head LUT (2048 entries); blocks 8-23 ext table
// ---------------------------------------------------------------------------
__global__ __launch_bounds__(256) void lut_kernel(
    const float* __restrict__ W1, const float* __restrict__ b1,
    const float* __restrict__ W2, const float* __restrict__ b2,
    const float* __restrict__ kc)
{
    const int blk = blockIdx.x;
    const int t = threadIdx.x;
    const float dmax = __uint_as_float(g_maxbits[0]) + __uint_as_float(g_maxbits[1]) + 1e-3f;
    const float step2 = dmax * dmax / (float)(LUT_N - 1);
    const float is2 = 1.0f / step2;

    if (blk >= 8) {
        const int j = (blk - 8) * 256 + t;
        const float* p = kc + (size_t)j * 3;
        const float x = p[0], y = p[1], z = p[2];
        float4 e;
        e.x = __uint_as_float(f2tf(-2.f * x * is2));
        e.y = __uint_as_float(f2tf(-2.f * y * is2));
        e.z = __uint_as_float(f2tf(-2.f * z * is2));
        e.w = __uint_as_float(f2tf(fmaf(x, x, fmaf(y, y, z * z)) * is2));
        g_ext[j] = e;
        return;
    }

    __shared__ float sW1[RBH], sb1[RBH], sW2[RBH * H_];
    if (t < RBH) { sW1[t] = W1[t]; sb1[t] = b1[t]; }
    for (int i = t; i < RBH * H_; i += 256) sW2[i] = W2[i];
    __syncthreads();

    if (blk == 0 && t == 0) g_inv_step2 = is2;

    int i = blk * 256 + t;
    float d = sqrtf(step2 * (float)i);

    float o[H_];
    #pragma unroll
    for (int hh = 0; hh < H_; hh++) o[hh] = b2[hh];
    #pragma unroll 8
    for (int j = 0; j < RBH; j++) {
        float x = fmaf(d, sW1[j], sb1[j]);
        float s = __fdividef(x, 1.0f + __expf(-x));
        #pragma unroll
        for (int hh = 0; hh < H_; hh++)
            o[hh] = fmaf(s, sW2[j * H_ + hh], o[hh]);
    }
    #pragma unroll
    for (int hh = 0; hh < H_; hh++)
        g_lut[hh * LUT_N + i] = o[hh] * LOG2E;
}

// ---------------------------------------------------------------------------
// fp16 GEMM body (unchanged): BMxBN, BK=32, 3-stage cp.async, LDSM.
// mode: 0 fp32 store, 1 fp16, 2 fp16*QSC, 3 fp16 transposed V store.
// ---------------------------------------------------------------------------
#define GASTR 40   // halves

template<int BM, int BN>
__device__ __forceinline__ void gemm_h_body(
    const __half* __restrict__ A, const __half* __restrict__ Bm,
    void* __restrict__ Cp, int N, int K, int row0, int mode, char* sm)
{
    constexpr int BSTR = BN + 8;
    constexpr int ASZ = BM * GASTR * 2;
    constexpr int BSZ = 32 * BSTR * 2;
    constexpr int MF  = BM / 64;
    constexpr int NFW = BN / 16;
    char* As = sm;
    char* Bs = sm + 3 * ASZ;

    const int tid = threadIdx.x;
    const int lane = tid & 31, wid = tid >> 5;
    const int wm = (wid >> 1) * (BM / 4), wn = (wid & 1) * (BN / 2);
    const int col0 = blockIdx.x * BN;
    const int lq = lane >> 2, lr = lane & 3;

    const int ar = (BM == 128) ? (tid >> 1) : (tid >> 2);
    const int ac = (BM == 128) ? ((tid & 1) * 16) : ((tid & 3) * 8);
    const int bk = tid >> 3;
    const int bn = (tid & 7) * ((BN == 128) ? 16 : 8);

    float acc[MF][NFW][4] = {};

    auto issue = [&](int k0) {
        const int st = (k0 >> 5) % 3;
        uint32_t a_s = s2u(As + st * ASZ + (ar * GASTR + ac) * 2);
        const __half* ag = A + (size_t)(row0 + ar) * K + k0 + ac;
        cpa16(a_s, ag);
        if (BM == 128) cpa16(a_s + 16, ag + 8);
        uint32_t b_s = s2u(Bs + st * BSZ + (bk * BSTR + bn) * 2);
        const __half* bg = Bm + (size_t)(k0 + bk) * N + col0 + bn;
        cpa16(b_s, bg);
        if (BN == 128) cpa16(b_s + 16, bg + 8);
        asm volatile("cp.async.commit_group;" ::: "memory");
    };

    issue(0); issue(32);

    const int a_lane = (lane & 15) * (GASTR * 2) + (lane >> 4) * 16;
    const int b_lane = ((lane & 7) + ((lane >> 3) & 1) * 8) * (BSTR * 2) + (lane >> 4) * 16;

    for (int k0 = 0; k0 < K; k0 += 32) {
        if (k0 + 64 < K) {
            asm volatile("cp.async.wait_group 1;" ::: "memory");
            __syncthreads();
            issue(k0 + 64);
        } else if (k0 + 32 < K) {
            asm volatile("cp.async.wait_group 1;" ::: "memory");
            __syncthreads();
        } else {
            asm volatile("cp.async.wait_group 0;" ::: "memory");
            __syncthreads();
        }
        const int st = (k0 >> 5) % 3;
        const uint32_t a_b = s2u(As + st * ASZ);
        const uint32_t b_b = s2u(Bs + st * BSZ);

        #pragma unroll
        for (int ks = 0; ks < 2; ks++) {
            uint32_t af[MF][4], bf[NFW / 2][4];
            #pragma unroll
            for (int mf = 0; mf < MF; mf++)
                ldsm4(af[mf], a_b + (wm + mf * 16) * (GASTR * 2) + ks * 32 + a_lane);
            #pragma unroll
            for (int n2 = 0; n2 < NFW / 2; n2++)
                ldsm4t(bf[n2], b_b + ks * 16 * (BSTR * 2) + (wn + n2 * 16) * 2 + b_lane);
            #pragma unroll
            for (int mf = 0; mf < MF; mf++)
                #pragma unroll
                for (int nf = 0; nf < NFW; nf++)
                    mma16(acc[mf][nf], af[mf], bf[nf >> 1][(nf & 1) * 2],
                          bf[nf >> 1][(nf & 1) * 2 + 1]);
        }
        __syncthreads();
    }

    #pragma unroll
    for (int mf = 0; mf < MF; mf++)
        #pragma unroll
        for (int nf = 0; nf < NFW; nf++) {
            const int r = row0 + wm + mf * 16 + lq;
            const int c = col0 + wn + nf * 8 + 2 * lr;
            float* v = acc[mf][nf];
            if (mode == 0) {
                float* C = (float*)Cp;
                *(float2*)&C[(size_t)r * N + c]       = make_float2(v[0], v[1]);
                *(float2*)&C[(size_t)(r + 8) * N + c] = make_float2(v[2], v[3]);
            } else if (mode == 3) {
                __half* C = (__half*)Cp;
                #pragma unroll
                for (int rw = 0; rw < 2; rw++) {
                    const int rr = r + rw * 8;
                    const int bb = rr >> 11, key = rr & 2047;
                    #pragma unroll
                    for (int cc = 0; cc < 2; cc++) {
                        const int col = c + cc;
                        C[(((size_t)bb * H_ + (col >> 6)) * HD_ + (col & 63)) * NK + key]
                            = __float2half_rn(v[rw * 2 + cc]);
                    }
                }
            } else {
                const float s = (mode == 2) ? QSC : 1.0f;
                __half* C = (__half*)Cp;
                *(uint32_t*)&C[(size_t)r * N + c]       = pk2h(v[0] * s, v[1] * s);
                *(uint32_t*)&C[(size_t)(r + 8) * N + c] = pk2h(v[2] * s, v[3] * s);
            }
        }
}

#define QKV_SMEM (3 * (128 * GASTR * 2 + 32 * 136 * 2))
#define OUT_SMEM (3 * (64 * GASTR * 2 + 32 * 72 * 2))

__global__ __launch_bounds__(256, 2) void gemm_qkv_kernel()
{
    extern __shared__ char gsm[];
    int by = blockIdx.y;
    const __half *A, *Bw; void* C; int mode;
    if (by < 16)      { A = g_QinH; Bw = g_WqH; C = g_Qh; mode = 2; }
    else if (by < 48) { A = g_KvH;  Bw = g_WkH; C = g_Kh; mode = 1; by -= 16; }
    else              { A = g_KvH;  Bw = g_WvH; C = g_Vh; mode = 3; by -= 48; }
    gemm_h_body<128, 128>(A, Bw, C, HID_, DIM_, by * 128, mode, gsm);
}

__global__ __launch_bounds__(256, 3) void gemm_out_kernel(float* __restrict__ out)
{
    extern __shared__ char gsm[];
    gemm_h_body<64, 64>(g_attnh, g_WoH, out, DIM_, HID_, blockIdx.y * 64, 0, gsm);
}

// ---------------------------------------------------------------------------
// fp16 flash attention: CTA split-K(2), no-max softmax, register-resident P,
// NEAREST-NEIGHBOR fp32 LUT (2048 entries), 3-stage cp.async ring,
// one __syncthreads per tile. 64 q x 1024 keys, 128 thr, 4 CTAs/SM.
// ---------------------------------------------------------------------------
#define AKT    32
#define KSTRH  72    // K tile halves/row (144B rows)
#define VSTRH  40    // V^T tile halves/row (80B rows)
#define KB_    4608  // AKT*KSTRH*2
#define EB_    512
#define VB_    5120  // HD_*VSTRH*2
#define STGB   (KB_ + EB_ + VB_)          // 10240 per stage
#define OFF_LUT (3 * STGB)                // 30720; 2048 fp32 = 8192 B
#define ATT_SMEM_BYTES (3 * STGB + 8192)  // 38912

__global__ __launch_bounds__(128, 4) void attn_kernel(const float* __restrict__ qc)
{
    extern __shared__ char smc[];
    float* slut = (float*)(smc + OFF_LUT);

    const int b   = blockIdx.z >> 1;
    const int ks_ = blockIdx.z & 1;
    const int h   = blockIdx.y;
    const int q0  = blockIdx.x * 64;
    const int tid = threadIdx.x;
    const int lane = tid & 31;
    const int w    = tid >> 5;
    const int lq   = lane >> 2;
    const int lr   = lane & 3;
    const int kstart = ks_ * (NK / 2);

    {   // stage fp32 LUT
        const float* lb = g_lut + h * LUT_N;
        for (int i = tid; i < LUT_N; i += 128) slut[i] = lb[i];
    }
    const float inv_step2 = g_inv_step2;

    // ldsm lane offsets (bytes)
    const int k_lane = (lane & 7) * (KSTRH * 2) + (lane >> 3) * 16;
    const int v_lane = (lane & 7) * (VSTRH * 2) + (lane >> 3) * 16;
    const int e_lane = lane * 16;

    // Q fragments
    uint32_t qa[4][4], qa2[4];
    float qn2s0, qn2s1;
    {
        const size_t r0 = ((size_t)(b * NQ + q0 + w * 16 + lq)) * HID_ + h * HD_;
        const size_t r1 = r0 + 8 * HID_;
        #pragma unroll
        for (int ks = 0; ks < 4; ks++) {
            qa[ks][0] = *(const uint32_t*)&g_Qh[r0 + ks * 16 + 2 * lr];
            qa[ks][1] = *(const uint32_t*)&g_Qh[r1 + ks * 16 + 2 * lr];
            qa[ks][2] = *(const uint32_t*)&g_Qh[r0 + ks * 16 + 2 * lr + 8];
            qa[ks][3] = *(const uint32_t*)&g_Qh[r1 + ks * 16 + 2 * lr + 8];
        }
        const float* p0 = qc + ((size_t)b * NQ + q0 + w * 16 + lq) * 3;
        const float* p1 = p0 + 8 * 3;
        float c0[4] = {p0[0], p0[1], p0[2], 1.0f};
        float c1[4] = {p1[0], p1[1], p1[2], 1.0f};
        qa2[0] = f2tf(c0[lr]);
        qa2[1] = f2tf(c1[lr]);
        qa2[2] = 0u; qa2[3] = 0u;
        qn2s0 = fmaf(c0[0], c0[0], fmaf(c0[1], c0[1], c0[2] * c0[2])) * inv_step2;
        qn2s1 = fmaf(c1[0], c1[0], fmaf(c1[1], c1[1], c1[2] * c1[2])) * inv_step2;
    }

    float of[8][4] = {};
    float l0 = 0.f, l1 = 0.f;

    const __half* Kp  = g_Kh + ((size_t)b * NK) * HID_ + h * HD_;
    const __half* Vpt = g_Vh + ((size_t)(b * H_ + h) * HD_) * NK;

    const int lkey = tid >> 2;
    const int qo   = (tid & 3) * 16;
    const int vrow = tid >> 1;
    const int vcb  = (tid & 1) * 16;

    auto issue = [&](int t) {
        char* stg = smc + (t % 3) * STGB;
        const __half* kg = Kp + (size_t)(kstart + t * AKT + lkey) * HID_ + qo;
        uint32_t kd = s2u(stg + (lkey * KSTRH + qo) * 2);
        cpa16(kd, kg); cpa16(kd + 16, kg + 8);
        if (tid < AKT)
            cpa16(s2u(stg + KB_ + tid * 16),
                  g_ext + (size_t)b * NK + kstart + t * AKT + tid);
        const __half* vg = Vpt + (size_t)vrow * NK + kstart + t * AKT + vcb;
        uint32_t vd = s2u(stg + KB_ + EB_ + (vrow * VSTRH + vcb) * 2);
        cpa16(vd, vg); cpa16(vd + 16, vg + 8);
        asm volatile("cp.async.commit_group;" ::: "memory");
    };

    const int NT = (NK / 2) / AKT;
    issue(0); issue(1);

    for (int t = 0; t < NT; t++) {
        if (t + 1 < NT) {
            asm volatile("cp.async.wait_group 1;" ::: "memory");
        } else {
            asm volatile("cp.async.wait_group 0;" ::: "memory");
        }
        __syncthreads();
        if (t + 2 < NT) issue(t + 2);

        char* stg = smc + (t % 3) * STGB;
        const uint32_t kb_s = s2u(stg);
        const uint32_t eb_s = s2u(stg + KB_);
        const uint32_t vb_s = s2u(stg + KB_ + EB_);

        // ---- QK^T ----
        float sacc[4][4] = {};
        #pragma unroll
        for (int nf = 0; nf < 4; nf++) {
            const uint32_t kbase = kb_s + nf * 8 * (KSTRH * 2) + k_lane;
            uint32_t kb[4];
            ldsm4(kb, kbase);
            mma16(sacc[nf], qa[0], kb[0], kb[1]);
            mma16(sacc[nf], qa[1], kb[2], kb[3]);
            ldsm4(kb, kbase + 64);
            mma16(sacc[nf], qa[2], kb[0], kb[1]);
            mma16(sacc[nf], qa[3], kb[2], kb[3]);
        }

        // ---- d^2 ext fragments ----
        uint32_t eb[4];
        ldsm4(eb, eb_s + e_lane);

        // ---- bias (nearest-neighbor LUT) + no-max softmax; P -> A-frags ----
        uint32_t pa[2][4];
        float ps0 = 0.f, ps1 = 0.f;
        #pragma unroll
        for (int nf = 0; nf < 4; nf++) {
            float dd4[4] = {qn2s0, qn2s0, qn2s1, qn2s1};
            mma8t(dd4, qa2, eb[nf]);
            float p4[4];
            #pragma unroll
            for (int j = 0; j < 4; j++) {
                float u = fminf(fmaxf(dd4[j], 0.f), (float)(LUT_N - 1));
                int ii = __float2int_rn(u);
                p4[j] = ex2(sacc[nf][j] + slut[ii]);
            }
            ps0 += p4[0] + p4[1];
            ps1 += p4[2] + p4[3];
            pa[nf >> 1][(nf & 1) * 2]     = pk2h(p4[0], p4[1]);
            pa[nf >> 1][(nf & 1) * 2 + 1] = pk2h(p4[2], p4[3]);
        }
        l0 += ps0;
        l1 += ps1;

        // ---- P V (P in registers, V via LDSM) ----
        #pragma unroll
        for (int nf = 0; nf < 8; nf++) {
            uint32_t vb[4];
            ldsm4(vb, vb_s + nf * 8 * (VSTRH * 2) + v_lane);
            mma16(of[nf], pa[0], vb[0], vb[1]);
            mma16(of[nf], pa[1], vb[2], vb[3]);
        }
    }

    // epilogue: unnormalized fp32 partial + l
    float* pO = ks_ ? g_O2 : g_attn;
    const size_t r0 = ((size_t)(b * NQ + q0 + w * 16 + lq)) * HID_ + h * HD_;
    const size_t r1 = r0 + 8 * HID_;
    #pragma unroll
    for (int nf = 0; nf < 8; nf++) {
        const int c = nf * 8 + 2 * lr;
        *(float2*)&pO[r0 + c] = make_float2(of[nf][0], of[nf][1]);
        *(float2*)&pO[r1 + c] = make_float2(of[nf][2], of[nf][3]);
    }
    l0 += __shfl_xor_sync(0xffffffffu, l0, 1);
    l0 += __shfl_xor_sync(0xffffffffu, l0, 2);
    l1 += __shfl_xor_sync(0xffffffffu, l1, 1);
    l1 += __shfl_xor_sync(0xffffffffu, l1, 2);
    if (lr == 0) {
        const size_t base = (((size_t)ks_ * B_ + b) * H_ + h) * NQ;
        const int qr = q0 + w * 16 + lq;
        g_l[base + qr]     = l0;
        g_l[base + qr + 8] = l1;
    }
}

// ---------------------------------------------------------------------------
__global__ __launch_bounds__(512) void merge_kernel()
{
    const int row = blockIdx.x;
    const int b = row >> 10;
    const int q = row & 1023;
    const int c = threadIdx.x;
    const int h = c >> 6;

    const float lA = g_l[(((size_t)0 * B_ + b) * H_ + h) * NQ + q];
    const float lB = g_l[(((size_t)1 * B_ + b) * H_ + h) * NQ + q];
    const float inv = __fdividef(1.f, lA + lB);

    const size_t o = (size_t)row * HID_ + c;
    g_attnh[o] = __float2half_rn((g_attn[o] + g_O2[o]) * inv);
}

// ---------------------------------------------------------------------------
extern "C" void kernel_launch(void* const* d_in, const int* in_sizes, int n_in,
                              void* d_out, int out_size)
{
    const float* q_in      = (const float*)d_in[0];
    const float* kv_in     = (const float*)d_in[1];
    const float* q_coords  = (const float*)d_in[2];
    const float* kv_coords = (const float*)d_in[3];
    const float* Wq        = (const float*)d_in[4];
    const float* Wk        = (const float*)d_in[5];
    const float* Wv        = (const float*)d_in[6];
    const float* Wo        = (const float*)d_in[7];
    const float* W1        = (const float*)d_in[8];
    const float* b1        = (const float*)d_in[9];
    const float* W2        = (const float*)d_in[10];
    const float* b2        = (const float*)d_in[11];
    float* out             = (float*)d_out;

    static bool attr_set = false;
    if (!attr_set) {
        cudaFuncSetAttribute(attn_kernel,
            cudaFuncAttributeMaxDynamicSharedMemorySize, ATT_SMEM_BYTES);
        cudaFuncSetAttribute(gemm_qkv_kernel,
            cudaFuncAttributeMaxDynamicSharedMemorySize, QKV_SMEM);
        cudaFuncSetAttribute(gemm_out_kernel,
            cudaFuncAttributeMaxDynamicSharedMemorySize, OUT_SMEM);
        attr_set = true;
    }

    conv_kernel<<<4096, 256>>>((const float4*)q_in, (const float4*)kv_in,
                               (const float4*)Wq, (const float4*)Wk,
                               (const float4*)Wv, (const float4*)Wo,
                               q_coords, kv_coords);
    // blocks 0-7: per-head LUT (2048); blocks 8-23: g_ext
    lut_kernel<<<24, 256>>>(W1, b1, W2, b2, kv_coords);

    gemm_qkv_kernel<<<dim3(HID_ / 128, 80), 256, QKV_SMEM>>>();

    attn_kernel<<<dim3(NQ / 64, H_, B_ * 2), 128, ATT_SMEM_BYTES>>>(q_coords);

    merge_kernel<<<B_ * NQ, 512>>>();

    gemm_out_kernel<<<dim3(DIM_ / 64, (B_ * NQ) / 64), 256, OUT_SMEM>>>(out);
}